// round 1
// baseline (speedup 1.0000x reference)
#include <cuda_runtime.h>

// ---------------------------------------------------------------------------
// Problem constants
// ---------------------------------------------------------------------------
constexpr int kN    = 512;
constexpr int kBZ   = 32;
constexpr int kTC   = 256;
constexpr int kF1   = 256;
constexpr int kF2   = 128;
constexpr int kE    = 524288;
constexpr int kNTOT = kBZ * kN;          // 16384
constexpr int kKTOT = kF2 * 2 * kN;      // 131072  (fcn1 inner dim)

// ---------------------------------------------------------------------------
// Scratch (single __device__ array; offsets in floats, all 16B aligned)
// ---------------------------------------------------------------------------
constexpr long OFF_LSLR = 0;                          // 16384 * 4
constexpr long OFF_A    = OFF_LSLR + (long)kNTOT * 4; // 32*512*512
constexpr long OFF_DISD = OFF_A    + (long)kBZ * kN * kN;
constexpr long OFF_XW1  = OFF_DISD + (long)kBZ * kN;
constexpr long OFF_H    = OFF_XW1  + (long)kBZ * kN * kF1;
constexpr long OFF_XW2  = OFF_H    + (long)kBZ * kN * kF1;
constexpr long OFF_EMB  = OFF_XW2  + (long)kBZ * kN * kF2;
constexpr long OFF_DISS = OFF_EMB  + (long)kNTOT * 256;
constexpr long OFF_DEGS = OFF_DISS + (long)kNTOT;     // used as int*
constexpr long OFF_XWS1 = OFF_DEGS + (long)kNTOT;
constexpr long OFF_SC1  = OFF_XWS1 + (long)kNTOT * kF1;
constexpr long OFF_XWS2 = OFF_SC1  + (long)kNTOT * kF1;
constexpr long OFF_H1   = OFF_XWS2 + (long)kNTOT * kF2;
constexpr long SCRATCH_FLOATS = OFF_H1 + (long)kBZ * 256;

__device__ __align__(16) float g_scratch[SCRATCH_FLOATS];

// ---------------------------------------------------------------------------
// Small kernels
// ---------------------------------------------------------------------------
__global__ void k_zero(int* degS, float* h1) {
    int i = blockIdx.x * 256 + threadIdx.x;
    if (i < kNTOT) degS[i] = 0;
    if (i < kBZ * 256) h1[i] = 0.f;
}

// per-node: u = relu(t); ls = u@Ws.T, lr = u@Wr.T  -> float4 (ls0,ls1,lr0,lr1)
__global__ void k_lslr(const float* __restrict__ t, const float* __restrict__ fcw,
                       float* __restrict__ lslr) {
    int warp = (blockIdx.x * blockDim.x + threadIdx.x) >> 5;
    int lane = threadIdx.x & 31;
    if (warp >= kNTOT) return;
    const float* tn = t + (long)warp * kTC;
    const float* w0 = fcw;          // row 0 of fc_cat_w (512 values)
    const float* w1 = fcw + 512;    // row 1
    float s0 = 0.f, s1 = 0.f, r0 = 0.f, r1 = 0.f;
#pragma unroll
    for (int q = 0; q < 8; q++) {
        int d = lane + 32 * q;
        float u = fmaxf(tn[d], 0.f);
        s0 += u * w0[d];       s1 += u * w1[d];
        r0 += u * w0[256 + d]; r1 += u * w1[256 + d];
    }
#pragma unroll
    for (int off = 16; off; off >>= 1) {
        s0 += __shfl_down_sync(0xffffffffu, s0, off);
        s1 += __shfl_down_sync(0xffffffffu, s1, off);
        r0 += __shfl_down_sync(0xffffffffu, r0, off);
        r1 += __shfl_down_sync(0xffffffffu, r1, off);
    }
    if (lane == 0)
        reinterpret_cast<float4*>(lslr)[warp] = make_float4(s0, s1, r0, r1);
}

// A[b][i][j] = (y0 >= y1), y_k = lr[i][k] + ls[j][k] + fc_cat_b[k] + gumbel
__global__ void k_buildA(const float* __restrict__ gu, const float* __restrict__ fcb,
                         const float* __restrict__ lslr, float* __restrict__ A) {
    int idx = blockIdx.x * 256 + threadIdx.x;   // < 16,777,216
    int j = idx & 511;
    int i = (idx >> 9) & 511;
    int b = idx >> 18;
    float2 u = reinterpret_cast<const float2*>(gu)[idx];
    float ux = fminf(fmaxf(u.x, 1e-9f), 1.0f - 1e-9f);
    float uy = fminf(fmaxf(u.y, 1e-9f), 1.0f - 1e-9f);
    float g0 = -logf(-logf(ux));
    float g1 = -logf(-logf(uy));
    float4 sj = reinterpret_cast<const float4*>(lslr)[b * kN + j];
    float4 si = reinterpret_cast<const float4*>(lslr)[b * kN + i];
    float y0 = si.z + sj.x + fcb[0] + g0;
    float y1 = si.w + sj.y + fcb[1] + g1;
    A[idx] = (y0 >= y1) ? 1.f : 0.f;
}

// dense degrees: deg[j] = 1 + sum_i A[i][j]; disD = rsqrt(deg)
__global__ void k_colsum(const float* __restrict__ A, float* __restrict__ disD) {
    int b = blockIdx.x;
    int j = threadIdx.x;
    const float* Ab = A + (long)b * kN * kN;
    float s = 1.f;
    for (int i = 0; i < kN; i++) s += Ab[(long)i * kN + j];
    disD[b * kN + j] = rsqrtf(s);
}

__global__ void k_degS(const int* __restrict__ colp, int* degS) {
    int e = blockIdx.x * 256 + threadIdx.x;
    if (e < kE) atomicAdd(&degS[colp[e]], 1);
}

__global__ void k_disS(const int* __restrict__ degS, float* __restrict__ disS) {
    int n = blockIdx.x * 256 + threadIdx.x;
    if (n < kNTOT) disS[n] = rsqrtf((float)degS[n] + 1.f);
}

// ---------------------------------------------------------------------------
// Generic fp32 NT GEMM:  C[M x Nf] = A[M x K] @ B[Nf x K]^T   (batched via z)
// BM=BN=64, BK=16, 256 threads, 4x4 micro-tile. M,Nf multiples of 64; K of 16.
// ---------------------------------------------------------------------------
template <bool RELU_A>
__global__ void k_gemm_nt(const float* __restrict__ A, long aStride,
                          const float* __restrict__ B,
                          float* __restrict__ C, long cStride,
                          int M, int Nf, int K) {
    __shared__ float As[16][64];
    __shared__ float Bs[16][64];
    const float* Ab = A + (long)blockIdx.z * aStride;
    float* Cb = C + (long)blockIdx.z * cStride;
    int m0 = blockIdx.y * 64, n0 = blockIdx.x * 64;
    int t = threadIdx.x;
    int lrow = t >> 2, lc = (t & 3) << 2;
    int tm = (t >> 4) << 2, tn = (t & 15) << 2;
    float acc[4][4];
#pragma unroll
    for (int i = 0; i < 4; i++)
#pragma unroll
        for (int j = 0; j < 4; j++) acc[i][j] = 0.f;

    for (int k0 = 0; k0 < K; k0 += 16) {
        float4 av = *reinterpret_cast<const float4*>(Ab + (long)(m0 + lrow) * K + k0 + lc);
        if (RELU_A) {
            av.x = fmaxf(av.x, 0.f); av.y = fmaxf(av.y, 0.f);
            av.z = fmaxf(av.z, 0.f); av.w = fmaxf(av.w, 0.f);
        }
        As[lc + 0][lrow] = av.x; As[lc + 1][lrow] = av.y;
        As[lc + 2][lrow] = av.z; As[lc + 3][lrow] = av.w;
        float4 bv = *reinterpret_cast<const float4*>(B + (long)(n0 + lrow) * K + k0 + lc);
        Bs[lc + 0][lrow] = bv.x; Bs[lc + 1][lrow] = bv.y;
        Bs[lc + 2][lrow] = bv.z; Bs[lc + 3][lrow] = bv.w;
        __syncthreads();
#pragma unroll
        for (int k = 0; k < 16; k++) {
            float a0 = As[k][tm], a1 = As[k][tm + 1], a2 = As[k][tm + 2], a3 = As[k][tm + 3];
            float b0 = Bs[k][tn], b1 = Bs[k][tn + 1], b2 = Bs[k][tn + 2], b3 = Bs[k][tn + 3];
            acc[0][0] += a0 * b0; acc[0][1] += a0 * b1; acc[0][2] += a0 * b2; acc[0][3] += a0 * b3;
            acc[1][0] += a1 * b0; acc[1][1] += a1 * b1; acc[1][2] += a1 * b2; acc[1][3] += a1 * b3;
            acc[2][0] += a2 * b0; acc[2][1] += a2 * b1; acc[2][2] += a2 * b2; acc[2][3] += a2 * b3;
            acc[3][0] += a3 * b0; acc[3][1] += a3 * b1; acc[3][2] += a3 * b2; acc[3][3] += a3 * b3;
        }
        __syncthreads();
    }
#pragma unroll
    for (int i = 0; i < 4; i++) {
        float4 v = make_float4(acc[i][0], acc[i][1], acc[i][2], acc[i][3]);
        *reinterpret_cast<float4*>(Cb + (long)(m0 + tm + i) * Nf + n0 + tn) = v;
    }
}

// ---------------------------------------------------------------------------
// Dense GCN propagation:
//   out[i][f] = dis[i] * ( sum_j A[j][i]*dis[j]*XW[j][f] + dis[i]*XW[i][f] ) + bias[f]
// A per-sample 512x512 row-major (j-major); BM=BN=64, BK=16.
// ---------------------------------------------------------------------------
template <bool RELU>
__global__ void k_prop(const float* __restrict__ A, const float* __restrict__ XW,
                       const float* __restrict__ dis, const float* __restrict__ bias,
                       float* __restrict__ out, int F, int outStride, int outOffset) {
    __shared__ float As[16][64];   // As[k][i]
    __shared__ float Bs[16][64];   // Bs[k][f] (pre-scaled by dis[j])
    int b = blockIdx.z;
    const float* Ab = A + (long)b * kN * kN;
    const float* Xb = XW + (long)b * kN * F;
    const float* db = dis + b * kN;
    float* Ob = out + (long)b * kN * outStride + outOffset;
    int i0 = blockIdx.y * 64, f0 = blockIdx.x * 64;
    int t = threadIdx.x;
    int kk = t >> 4, c4 = (t & 15) << 2;
    int tm = (t >> 4) << 2, tn = (t & 15) << 2;
    float acc[4][4];
#pragma unroll
    for (int i = 0; i < 4; i++)
#pragma unroll
        for (int j = 0; j < 4; j++) acc[i][j] = 0.f;

    for (int j0 = 0; j0 < kN; j0 += 16) {
        float dj = db[j0 + kk];
        float4 av = *reinterpret_cast<const float4*>(Ab + (long)(j0 + kk) * kN + i0 + c4);
        *reinterpret_cast<float4*>(&As[kk][c4]) = av;
        float4 xv = *reinterpret_cast<const float4*>(Xb + (long)(j0 + kk) * F + f0 + c4);
        xv.x *= dj; xv.y *= dj; xv.z *= dj; xv.w *= dj;
        *reinterpret_cast<float4*>(&Bs[kk][c4]) = xv;
        __syncthreads();
#pragma unroll
        for (int k = 0; k < 16; k++) {
            float a0 = As[k][tm], a1 = As[k][tm + 1], a2 = As[k][tm + 2], a3 = As[k][tm + 3];
            float b0 = Bs[k][tn], b1 = Bs[k][tn + 1], b2 = Bs[k][tn + 2], b3 = Bs[k][tn + 3];
            acc[0][0] += a0 * b0; acc[0][1] += a0 * b1; acc[0][2] += a0 * b2; acc[0][3] += a0 * b3;
            acc[1][0] += a1 * b0; acc[1][1] += a1 * b1; acc[1][2] += a1 * b2; acc[1][3] += a1 * b3;
            acc[2][0] += a2 * b0; acc[2][1] += a2 * b1; acc[2][2] += a2 * b2; acc[2][3] += a2 * b3;
            acc[3][0] += a3 * b0; acc[3][1] += a3 * b1; acc[3][2] += a3 * b2; acc[3][3] += a3 * b3;
        }
        __syncthreads();
    }
    float4 bb = *reinterpret_cast<const float4*>(bias + f0 + tn);
#pragma unroll
    for (int i = 0; i < 4; i++) {
        int ii = i0 + tm + i;
        float di = db[ii];
        float4 xw = *reinterpret_cast<const float4*>(Xb + (long)ii * F + f0 + tn);
        float v0 = di * (acc[i][0] + di * xw.x) + bb.x;
        float v1 = di * (acc[i][1] + di * xw.y) + bb.y;
        float v2 = di * (acc[i][2] + di * xw.z) + bb.z;
        float v3 = di * (acc[i][3] + di * xw.w) + bb.w;
        if (RELU) {
            v0 = fmaxf(v0, 0.f); v1 = fmaxf(v1, 0.f);
            v2 = fmaxf(v2, 0.f); v3 = fmaxf(v3, 0.f);
        }
        *reinterpret_cast<float4*>(Ob + (long)ii * outStride + f0 + tn) =
            make_float4(v0, v1, v2, v3);
    }
}

// ---------------------------------------------------------------------------
// Sparse GCN helpers
// ---------------------------------------------------------------------------
// out[n][f] = xw[n][f]*dis[n]^2 + bias[f]   (self-loop + bias init)
__global__ void k_init_sc(const float* __restrict__ xw, const float* __restrict__ disS,
                          const float* __restrict__ bias, float* __restrict__ out,
                          int F, int outStride, int outOffset, int logF) {
    int idx = blockIdx.x * 256 + threadIdx.x;   // NTOT * F
    int n = idx >> logF;
    int f = idx & (F - 1);
    float d = disS[n];
    out[(long)n * outStride + outOffset + f] = xw[idx] * d * d + bias[f];
}

// edge scatter with float4 atomics: out[c] += xw[r] * dis[r]*dis[c]
template <int LOGFQ>   // FQ = F/4 = 1<<LOGFQ
__global__ void k_scatter(const int* __restrict__ rowp, const int* __restrict__ colp,
                          const float* __restrict__ xw, const float* __restrict__ disS,
                          float* __restrict__ out, int F, int outStride, int outOffset) {
    int idx = blockIdx.x * 256 + threadIdx.x;
    int e = idx >> LOGFQ;
    int q = (idx & ((1 << LOGFQ) - 1)) << 2;
    int r = rowp[e], c = colp[e];
    float s = disS[r] * disS[c];
    float4 v = *reinterpret_cast<const float4*>(xw + (long)r * F + q);
    v.x *= s; v.y *= s; v.z *= s; v.w *= s;
    atomicAdd(reinterpret_cast<float4*>(out + (long)c * outStride + outOffset + q), v);
}

// ---------------------------------------------------------------------------
// fcn1 split-K:  h1[32][256] += emb[32][131072] @ fcn1_w[256][131072]^T
// grid = (256/64 n-tiles, 128 K-chunks), 256 threads, KC=1024
// ---------------------------------------------------------------------------
__global__ void k_fcn1(const float* __restrict__ emb, const float* __restrict__ W,
                       float* __restrict__ h1) {
    constexpr int KC = kKTOT / 128;  // 1024
    __shared__ float As[16][32];
    __shared__ float Bs[16][64];
    int n0 = blockIdx.x * 64;
    int kbase = blockIdx.y * KC;
    int t = threadIdx.x;
    int m = t & 31;
    int nb = (t >> 5) << 3;
    float acc[8];
#pragma unroll
    for (int j = 0; j < 8; j++) acc[j] = 0.f;

    for (int k0 = kbase; k0 < kbase + KC; k0 += 16) {
        if (t < 128) {
            int row = t >> 2, c4 = (t & 3) << 2;
            float4 a = *reinterpret_cast<const float4*>(emb + (long)row * kKTOT + k0 + c4);
            As[c4 + 0][row] = a.x; As[c4 + 1][row] = a.y;
            As[c4 + 2][row] = a.z; As[c4 + 3][row] = a.w;
        }
        {
            int row = t >> 2, c4 = (t & 3) << 2;
            float4 b = *reinterpret_cast<const float4*>(W + (long)(n0 + row) * kKTOT + k0 + c4);
            Bs[c4 + 0][row] = b.x; Bs[c4 + 1][row] = b.y;
            Bs[c4 + 2][row] = b.z; Bs[c4 + 3][row] = b.w;
        }
        __syncthreads();
#pragma unroll
        for (int k = 0; k < 16; k++) {
            float a = As[k][m];
#pragma unroll
            for (int j = 0; j < 8; j++) acc[j] += a * Bs[k][nb + j];
        }
        __syncthreads();
    }
#pragma unroll
    for (int j = 0; j < 8; j++)
        atomicAdd(&h1[m * 256 + n0 + nb + j], acc[j]);
}

// ---------------------------------------------------------------------------
// fcn2 + fcn3 (tiny): one block, 1024 threads
// ---------------------------------------------------------------------------
__global__ void k_fcn23(const float* __restrict__ h1g,
                        const float* __restrict__ b1, const float* __restrict__ w2,
                        const float* __restrict__ b2, const float* __restrict__ w3,
                        const float* __restrict__ b3, float* __restrict__ out) {
    __shared__ float h1s[32][256];
    __shared__ float h2s[32][32];
    int t = threadIdx.x;
    for (int idx = t; idx < 32 * 256; idx += 1024) {
        float v = h1g[idx] + b1[idx & 255];
        h1s[idx >> 8][idx & 255] = (v >= 0.f) ? v : 0.2f * v;
    }
    __syncthreads();
    {
        int b = t >> 5, o = t & 31;
        float s = 0.f;
#pragma unroll 8
        for (int k = 0; k < 256; k++) s += h1s[b][k] * w2[o * 256 + k];
        s += b2[o];
        h2s[b][o] = (s >= 0.f) ? s : 0.2f * s;
    }
    __syncthreads();
    if (t < 64) {
        int b = t >> 1, o = t & 1;
        float s = 0.f;
#pragma unroll
        for (int k = 0; k < 32; k++) s += h2s[b][k] * w3[o * 32 + k];
        out[b * 2 + o] = s + b3[o];
    }
}

// ---------------------------------------------------------------------------
// Launch
// ---------------------------------------------------------------------------
extern "C" void kernel_launch(void* const* d_in, const int* in_sizes, int n_in,
                              void* d_out, int out_size) {
    const float* x    = (const float*)d_in[0];
    const float* t    = (const float*)d_in[1];
    const float* gu   = (const float*)d_in[2];
    const int*   ei   = (const int*)d_in[3];
    const float* w1   = (const float*)d_in[4];
    const float* b1   = (const float*)d_in[5];
    const float* w2   = (const float*)d_in[6];
    const float* b2   = (const float*)d_in[7];
    const float* fcw  = (const float*)d_in[8];
    const float* fcb  = (const float*)d_in[9];
    const float* f1w  = (const float*)d_in[10];
    const float* f1b  = (const float*)d_in[11];
    const float* f2w  = (const float*)d_in[12];
    const float* f2b  = (const float*)d_in[13];
    const float* f3w  = (const float*)d_in[14];
    const float* f3b  = (const float*)d_in[15];
    float* out = (float*)d_out;

    const int* rowp = ei;
    const int* colp = ei + kE;

    float* base = nullptr;
    cudaGetSymbolAddress((void**)&base, g_scratch);
    float* p_lslr = base + OFF_LSLR;
    float* p_A    = base + OFF_A;
    float* p_disD = base + OFF_DISD;
    float* p_xw1  = base + OFF_XW1;
    float* p_h    = base + OFF_H;
    float* p_xw2  = base + OFF_XW2;
    float* p_emb  = base + OFF_EMB;
    float* p_disS = base + OFF_DISS;
    int*   p_degS = (int*)(base + OFF_DEGS);
    float* p_xws1 = base + OFF_XWS1;
    float* p_sc1  = base + OFF_SC1;
    float* p_xws2 = base + OFF_XWS2;
    float* p_h1   = base + OFF_H1;

    // init
    k_zero<<<64, 256>>>(p_degS, p_h1);

    // Gumbel adjacency
    k_lslr<<<kNTOT / 8, 256>>>(t, fcw, p_lslr);
    k_buildA<<<kBZ * kN * kN / 256, 256>>>(gu, fcb, p_lslr, p_A);
    k_colsum<<<kBZ, kN>>>(p_A, p_disD);

    // sparse degrees
    k_degS<<<kE / 256, 256>>>(colp, p_degS);
    k_disS<<<kNTOT / 256, 256>>>(p_degS, p_disS);

    // dense GCN layer 1:  xw1 = x @ W1^T ; h = relu(prop(xw1)) + b1
    k_gemm_nt<false><<<dim3(kF1 / 64, kN / 64, kBZ), 256>>>(
        x, (long)kN * kN, w1, p_xw1, (long)kN * kF1, kN, kF1, kN);
    k_prop<true><<<dim3(kF1 / 64, kN / 64, kBZ), 256>>>(
        p_A, p_xw1, p_disD, b1, p_h, kF1, kF1, 0);

    // dense GCN layer 2 -> emb[:, 0:128]
    k_gemm_nt<false><<<dim3(kF2 / 64, kN / 64, kBZ), 256>>>(
        p_h, (long)kN * kF1, w2, p_xw2, (long)kN * kF2, kN, kF2, kF1);
    k_prop<false><<<dim3(kF2 / 64, kN / 64, kBZ), 256>>>(
        p_A, p_xw2, p_disD, b2, p_emb, kF2, 256, 0);

    // sparse GCN layer 1
    k_gemm_nt<false><<<dim3(kF1 / 64, kNTOT / 64, 1), 256>>>(
        x, 0, w1, p_xws1, 0, kNTOT, kF1, kN);
    k_init_sc<<<kNTOT * kF1 / 256, 256>>>(p_xws1, p_disS, b1, p_sc1, kF1, kF1, 0, 8);
    k_scatter<6><<<kE * (kF1 / 4) / 256, 256>>>(rowp, colp, p_xws1, p_disS,
                                                p_sc1, kF1, kF1, 0);

    // sparse GCN layer 2 -> emb[:, 128:256]  (relu applied on GEMM A-load)
    k_gemm_nt<true><<<dim3(kF2 / 64, kNTOT / 64, 1), 256>>>(
        p_sc1, 0, w2, p_xws2, 0, kNTOT, kF2, kF1);
    k_init_sc<<<kNTOT * kF2 / 256, 256>>>(p_xws2, p_disS, b2, p_emb, kF2, 256, 128, 7);
    k_scatter<5><<<kE * (kF2 / 4) / 256, 256>>>(rowp, colp, p_xws2, p_disS,
                                                p_emb, kF2, 256, 128);

    // MLP head
    k_fcn1<<<dim3(256 / 64, 128), 256>>>(p_emb, f1w, p_h1);
    k_fcn23<<<1, 1024>>>(p_h1, f1b, f2w, f2b, f3w, f3b, out);
}

// round 2
// speedup vs baseline: 1.0912x; 1.0912x over previous
#include <cuda_runtime.h>

// ---------------------------------------------------------------------------
// Problem constants
// ---------------------------------------------------------------------------
constexpr int kN    = 512;
constexpr int kBZ   = 32;
constexpr int kTC   = 256;
constexpr int kF1   = 256;
constexpr int kF2   = 128;
constexpr int kE    = 524288;
constexpr int kNTOT = kBZ * kN;          // 16384
constexpr int kKTOT = kF2 * 2 * kN;      // 131072  (fcn1 inner dim)

// ---------------------------------------------------------------------------
// Scratch
// ---------------------------------------------------------------------------
constexpr long OFF_LSLR = 0;                          // 16384 * 4
constexpr long OFF_A    = OFF_LSLR + (long)kNTOT * 4; // 32*512*512
constexpr long OFF_DISD = OFF_A    + (long)kBZ * kN * kN;
constexpr long OFF_XW1  = OFF_DISD + (long)kBZ * kN;
constexpr long OFF_H    = OFF_XW1  + (long)kBZ * kN * kF1;
constexpr long OFF_XW2  = OFF_H    + (long)kBZ * kN * kF1;
constexpr long OFF_EMB  = OFF_XW2  + (long)kBZ * kN * kF2;
constexpr long OFF_DISS = OFF_EMB  + (long)kNTOT * 256;
constexpr long OFF_DEGS = OFF_DISS + (long)kNTOT;     // used as int*
constexpr long OFF_XWS1 = OFF_DEGS + (long)kNTOT;
constexpr long OFF_SC1  = OFF_XWS1 + (long)kNTOT * kF1;
constexpr long OFF_XWS2 = OFF_SC1  + (long)kNTOT * kF1;
constexpr long OFF_H1   = OFF_XWS2 + (long)kNTOT * kF2;
constexpr long OFF_DEGD = OFF_H1   + (long)kBZ * 256;
constexpr long SCRATCH_FLOATS = OFF_DEGD + (long)kNTOT;

__device__ __align__(16) float g_scratch[SCRATCH_FLOATS];

// ---------------------------------------------------------------------------
// Small kernels
// ---------------------------------------------------------------------------
__global__ void k_zero(int* degS, float* h1, float* degD) {
    int i = blockIdx.x * 256 + threadIdx.x;
    if (i < kNTOT) { degS[i] = 0; degD[i] = 1.f; }
    if (i < kBZ * 256) h1[i] = 0.f;
}

// per-node: u = relu(t); ls = u@Ws.T, lr = u@Wr.T  -> float4 (ls0,ls1,lr0,lr1)
__global__ void k_lslr(const float* __restrict__ t, const float* __restrict__ fcw,
                       float* __restrict__ lslr) {
    int warp = (blockIdx.x * blockDim.x + threadIdx.x) >> 5;
    int lane = threadIdx.x & 31;
    if (warp >= kNTOT) return;
    const float* tn = t + (long)warp * kTC;
    const float* w0 = fcw;
    const float* w1 = fcw + 512;
    float s0 = 0.f, s1 = 0.f, r0 = 0.f, r1 = 0.f;
#pragma unroll
    for (int q = 0; q < 8; q++) {
        int d = lane + 32 * q;
        float u = fmaxf(tn[d], 0.f);
        s0 += u * w0[d];       s1 += u * w1[d];
        r0 += u * w0[256 + d]; r1 += u * w1[256 + d];
    }
#pragma unroll
    for (int off = 16; off; off >>= 1) {
        s0 += __shfl_down_sync(0xffffffffu, s0, off);
        s1 += __shfl_down_sync(0xffffffffu, s1, off);
        r0 += __shfl_down_sync(0xffffffffu, r0, off);
        r1 += __shfl_down_sync(0xffffffffu, r1, off);
    }
    if (lane == 0)
        reinterpret_cast<float4*>(lslr)[warp] = make_float4(s0, s1, r0, r1);
}

__global__ void k_buildA(const float* __restrict__ gu, const float* __restrict__ fcb,
                         const float* __restrict__ lslr, float* __restrict__ A) {
    int idx = blockIdx.x * 256 + threadIdx.x;
    int j = idx & 511;
    int i = (idx >> 9) & 511;
    int b = idx >> 18;
    float2 u = reinterpret_cast<const float2*>(gu)[idx];
    float ux = fminf(fmaxf(u.x, 1e-9f), 1.0f - 1e-9f);
    float uy = fminf(fmaxf(u.y, 1e-9f), 1.0f - 1e-9f);
    float g0 = -logf(-logf(ux));
    float g1 = -logf(-logf(uy));
    float4 sj = reinterpret_cast<const float4*>(lslr)[b * kN + j];
    float4 si = reinterpret_cast<const float4*>(lslr)[b * kN + i];
    float y0 = si.z + sj.x + fcb[0] + g0;
    float y1 = si.w + sj.y + fcb[1] + g1;
    A[idx] = (y0 >= y1) ? 1.f : 0.f;
}

// partial column sums of A (64 rows per block) -> atomic into degD (init 1.0)
__global__ void k_colsum_part(const float* __restrict__ A, float* __restrict__ degD) {
    int b = blockIdx.x;
    int j = threadIdx.x;
    int r0 = blockIdx.y * 64;
    const float* Ab = A + (long)b * kN * kN;
    float s = 0.f;
#pragma unroll 8
    for (int r = r0; r < r0 + 64; r++) s += Ab[(long)r * kN + j];
    atomicAdd(&degD[b * kN + j], s);
}

__global__ void k_rsqrtD(const float* __restrict__ degD, float* __restrict__ disD) {
    int i = blockIdx.x * 256 + threadIdx.x;
    if (i < kNTOT) disD[i] = rsqrtf(degD[i]);
}

__global__ void k_degS(const int* __restrict__ colp, int* degS) {
    int e = blockIdx.x * 256 + threadIdx.x;
    if (e < kE) atomicAdd(&degS[colp[e]], 1);
}

__global__ void k_disS(const int* __restrict__ degS, float* __restrict__ disS) {
    int n = blockIdx.x * 256 + threadIdx.x;
    if (n < kNTOT) disS[n] = rsqrtf((float)degS[n] + 1.f);
}

// ---------------------------------------------------------------------------
// 128x128x8 double-buffered fp32 NT GEMM: C[MxNf] = A[MxK] @ B[NfxK]^T
// 256 threads, 8x8 micro-tile.  M mult of 128 (via grid.y), Nf mult of 128,
// K mult of 8.  Batched via blockIdx.z / strides.
// ---------------------------------------------------------------------------
template <bool RELU_A>
__global__ __launch_bounds__(256) void k_gemm128(
        const float* __restrict__ A, long aStride,
        const float* __restrict__ B,
        float* __restrict__ C, long cStride,
        int Nf, int K) {
    __shared__ float As[2][8][128];
    __shared__ float Bs[2][8][128];
    const float* Ab = A + (long)blockIdx.z * aStride;
    float* Cb = C + (long)blockIdx.z * cStride;
    int m0 = blockIdx.y * 128, n0 = blockIdx.x * 128;
    int t = threadIdx.x;
    int lrow = t >> 1, lc = (t & 1) << 2;        // tile loads
    int tm = (t >> 4) << 3, tn = (t & 15) << 3;  // micro-tile
    float acc[8][8];
#pragma unroll
    for (int i = 0; i < 8; i++)
#pragma unroll
        for (int j = 0; j < 8; j++) acc[i][j] = 0.f;

    const float* aPtr = Ab + (long)(m0 + lrow) * K + lc;
    const float* bPtr = B + (long)(n0 + lrow) * K + lc;

    // prefetch tile 0
    {
        float4 av = *reinterpret_cast<const float4*>(aPtr);
        float4 bv = *reinterpret_cast<const float4*>(bPtr);
        if (RELU_A) {
            av.x = fmaxf(av.x, 0.f); av.y = fmaxf(av.y, 0.f);
            av.z = fmaxf(av.z, 0.f); av.w = fmaxf(av.w, 0.f);
        }
        As[0][lc + 0][lrow] = av.x; As[0][lc + 1][lrow] = av.y;
        As[0][lc + 2][lrow] = av.z; As[0][lc + 3][lrow] = av.w;
        Bs[0][lc + 0][lrow] = bv.x; Bs[0][lc + 1][lrow] = bv.y;
        Bs[0][lc + 2][lrow] = bv.z; Bs[0][lc + 3][lrow] = bv.w;
    }
    __syncthreads();

    int buf = 0;
    for (int k0 = 0; k0 < K; k0 += 8) {
        bool more = (k0 + 8) < K;
        float4 an, bn;
        if (more) {
            an = *reinterpret_cast<const float4*>(aPtr + k0 + 8);
            bn = *reinterpret_cast<const float4*>(bPtr + k0 + 8);
            if (RELU_A) {
                an.x = fmaxf(an.x, 0.f); an.y = fmaxf(an.y, 0.f);
                an.z = fmaxf(an.z, 0.f); an.w = fmaxf(an.w, 0.f);
            }
        }
#pragma unroll
        for (int k = 0; k < 8; k++) {
            float a[8], b[8];
            *reinterpret_cast<float4*>(a)     = *reinterpret_cast<float4*>(&As[buf][k][tm]);
            *reinterpret_cast<float4*>(a + 4) = *reinterpret_cast<float4*>(&As[buf][k][tm + 4]);
            *reinterpret_cast<float4*>(b)     = *reinterpret_cast<float4*>(&Bs[buf][k][tn]);
            *reinterpret_cast<float4*>(b + 4) = *reinterpret_cast<float4*>(&Bs[buf][k][tn + 4]);
#pragma unroll
            for (int i = 0; i < 8; i++)
#pragma unroll
                for (int j = 0; j < 8; j++) acc[i][j] += a[i] * b[j];
        }
        if (more) {
            int nb = buf ^ 1;
            As[nb][lc + 0][lrow] = an.x; As[nb][lc + 1][lrow] = an.y;
            As[nb][lc + 2][lrow] = an.z; As[nb][lc + 3][lrow] = an.w;
            Bs[nb][lc + 0][lrow] = bn.x; Bs[nb][lc + 1][lrow] = bn.y;
            Bs[nb][lc + 2][lrow] = bn.z; Bs[nb][lc + 3][lrow] = bn.w;
            __syncthreads();
            buf = nb;
        }
    }
#pragma unroll
    for (int i = 0; i < 8; i++) {
        float* cp = Cb + (long)(m0 + tm + i) * Nf + n0 + tn;
        *reinterpret_cast<float4*>(cp)     = make_float4(acc[i][0], acc[i][1], acc[i][2], acc[i][3]);
        *reinterpret_cast<float4*>(cp + 4) = make_float4(acc[i][4], acc[i][5], acc[i][6], acc[i][7]);
    }
}

// ---------------------------------------------------------------------------
// Dense GCN propagation, 128x128x8 double-buffered:
//   out[i][f] = dis[i]*( sum_j A[j][i]*dis[j]*XW[j][f] + dis[i]*XW[i][f] ) + b[f]
// ---------------------------------------------------------------------------
template <bool RELU>
__global__ __launch_bounds__(256) void k_prop128(
        const float* __restrict__ A, const float* __restrict__ XW,
        const float* __restrict__ dis, const float* __restrict__ bias,
        float* __restrict__ out, int F, int outStride, int outOffset) {
    __shared__ float As[2][8][128];
    __shared__ float Bs[2][8][128];
    int b = blockIdx.z;
    const float* Ab = A + (long)b * kN * kN;
    const float* Xb = XW + (long)b * kN * F;
    const float* db = dis + b * kN;
    float* Ob = out + (long)b * kN * outStride + outOffset;
    int i0 = blockIdx.y * 128, f0 = blockIdx.x * 128;
    int t = threadIdx.x;
    int kk = t >> 5, c4 = (t & 31) << 2;
    int tm = (t >> 4) << 3, tn = (t & 15) << 3;
    float acc[8][8];
#pragma unroll
    for (int i = 0; i < 8; i++)
#pragma unroll
        for (int j = 0; j < 8; j++) acc[i][j] = 0.f;

    // prefetch tile 0
    {
        float dj = db[kk];
        float4 av = *reinterpret_cast<const float4*>(Ab + (long)kk * kN + i0 + c4);
        float4 xv = *reinterpret_cast<const float4*>(Xb + (long)kk * F + f0 + c4);
        xv.x *= dj; xv.y *= dj; xv.z *= dj; xv.w *= dj;
        *reinterpret_cast<float4*>(&As[0][kk][c4]) = av;
        *reinterpret_cast<float4*>(&Bs[0][kk][c4]) = xv;
    }
    __syncthreads();

    int buf = 0;
    for (int j0 = 0; j0 < kN; j0 += 8) {
        bool more = (j0 + 8) < kN;
        float4 an, xn;
        if (more) {
            float djn = db[j0 + 8 + kk];
            an = *reinterpret_cast<const float4*>(Ab + (long)(j0 + 8 + kk) * kN + i0 + c4);
            xn = *reinterpret_cast<const float4*>(Xb + (long)(j0 + 8 + kk) * F + f0 + c4);
            xn.x *= djn; xn.y *= djn; xn.z *= djn; xn.w *= djn;
        }
#pragma unroll
        for (int k = 0; k < 8; k++) {
            float a[8], bb[8];
            *reinterpret_cast<float4*>(a)      = *reinterpret_cast<float4*>(&As[buf][k][tm]);
            *reinterpret_cast<float4*>(a + 4)  = *reinterpret_cast<float4*>(&As[buf][k][tm + 4]);
            *reinterpret_cast<float4*>(bb)     = *reinterpret_cast<float4*>(&Bs[buf][k][tn]);
            *reinterpret_cast<float4*>(bb + 4) = *reinterpret_cast<float4*>(&Bs[buf][k][tn + 4]);
#pragma unroll
            for (int i = 0; i < 8; i++)
#pragma unroll
                for (int j = 0; j < 8; j++) acc[i][j] += a[i] * bb[j];
        }
        if (more) {
            int nb = buf ^ 1;
            *reinterpret_cast<float4*>(&As[nb][kk][c4]) = an;
            *reinterpret_cast<float4*>(&Bs[nb][kk][c4]) = xn;
            __syncthreads();
            buf = nb;
        }
    }

    float4 bb0 = *reinterpret_cast<const float4*>(bias + f0 + tn);
    float4 bb1 = *reinterpret_cast<const float4*>(bias + f0 + tn + 4);
#pragma unroll
    for (int i = 0; i < 8; i++) {
        int ii = i0 + tm + i;
        float di = db[ii];
        float4 x0 = *reinterpret_cast<const float4*>(Xb + (long)ii * F + f0 + tn);
        float4 x1 = *reinterpret_cast<const float4*>(Xb + (long)ii * F + f0 + tn + 4);
        float v0 = di * (acc[i][0] + di * x0.x) + bb0.x;
        float v1 = di * (acc[i][1] + di * x0.y) + bb0.y;
        float v2 = di * (acc[i][2] + di * x0.z) + bb0.z;
        float v3 = di * (acc[i][3] + di * x0.w) + bb0.w;
        float v4 = di * (acc[i][4] + di * x1.x) + bb1.x;
        float v5 = di * (acc[i][5] + di * x1.y) + bb1.y;
        float v6 = di * (acc[i][6] + di * x1.z) + bb1.z;
        float v7 = di * (acc[i][7] + di * x1.w) + bb1.w;
        if (RELU) {
            v0 = fmaxf(v0, 0.f); v1 = fmaxf(v1, 0.f); v2 = fmaxf(v2, 0.f); v3 = fmaxf(v3, 0.f);
            v4 = fmaxf(v4, 0.f); v5 = fmaxf(v5, 0.f); v6 = fmaxf(v6, 0.f); v7 = fmaxf(v7, 0.f);
        }
        float* op = Ob + (long)ii * outStride + f0 + tn;
        *reinterpret_cast<float4*>(op)     = make_float4(v0, v1, v2, v3);
        *reinterpret_cast<float4*>(op + 4) = make_float4(v4, v5, v6, v7);
    }
}

// ---------------------------------------------------------------------------
// Sparse GCN helpers
// ---------------------------------------------------------------------------
__global__ void k_init_sc(const float* __restrict__ xw, const float* __restrict__ disS,
                          const float* __restrict__ bias, float* __restrict__ out,
                          int F, int outStride, int outOffset, int logF) {
    int idx = blockIdx.x * 256 + threadIdx.x;
    int n = idx >> logF;
    int f = idx & (F - 1);
    float d = disS[n];
    out[(long)n * outStride + outOffset + f] = xw[idx] * d * d + bias[f];
}

template <int LOGFQ>
__global__ void k_scatter(const int* __restrict__ rowp, const int* __restrict__ colp,
                          const float* __restrict__ xw, const float* __restrict__ disS,
                          float* __restrict__ out, int F, int outStride, int outOffset) {
    int idx = blockIdx.x * 256 + threadIdx.x;
    int e = idx >> LOGFQ;
    int q = (idx & ((1 << LOGFQ) - 1)) << 2;
    int r = rowp[e], c = colp[e];
    float s = disS[r] * disS[c];
    float4 v = *reinterpret_cast<const float4*>(xw + (long)r * F + q);
    v.x *= s; v.y *= s; v.z *= s; v.w *= s;
    atomicAdd(reinterpret_cast<float4*>(out + (long)c * outStride + outOffset + q), v);
}

// ---------------------------------------------------------------------------
// fcn1 split-K (bandwidth-bound on 134 MB weight read)
// ---------------------------------------------------------------------------
__global__ void k_fcn1(const float* __restrict__ emb, const float* __restrict__ W,
                       float* __restrict__ h1) {
    constexpr int KC = kKTOT / 128;  // 1024
    __shared__ float As[16][32];
    __shared__ float Bs[16][64];
    int n0 = blockIdx.x * 64;
    int kbase = blockIdx.y * KC;
    int t = threadIdx.x;
    int m = t & 31;
    int nb = (t >> 5) << 3;
    float acc[8];
#pragma unroll
    for (int j = 0; j < 8; j++) acc[j] = 0.f;

    for (int k0 = kbase; k0 < kbase + KC; k0 += 16) {
        if (t < 128) {
            int row = t >> 2, c4 = (t & 3) << 2;
            float4 a = *reinterpret_cast<const float4*>(emb + (long)row * kKTOT + k0 + c4);
            As[c4 + 0][row] = a.x; As[c4 + 1][row] = a.y;
            As[c4 + 2][row] = a.z; As[c4 + 3][row] = a.w;
        }
        {
            int row = t >> 2, c4 = (t & 3) << 2;
            float4 b = *reinterpret_cast<const float4*>(W + (long)(n0 + row) * kKTOT + k0 + c4);
            Bs[c4 + 0][row] = b.x; Bs[c4 + 1][row] = b.y;
            Bs[c4 + 2][row] = b.z; Bs[c4 + 3][row] = b.w;
        }
        __syncthreads();
#pragma unroll
        for (int k = 0; k < 16; k++) {
            float a = As[k][m];
#pragma unroll
            for (int j = 0; j < 8; j++) acc[j] += a * Bs[k][nb + j];
        }
        __syncthreads();
    }
#pragma unroll
    for (int j = 0; j < 8; j++)
        atomicAdd(&h1[m * 256 + n0 + nb + j], acc[j]);
}

__global__ void k_fcn23(const float* __restrict__ h1g,
                        const float* __restrict__ b1, const float* __restrict__ w2,
                        const float* __restrict__ b2, const float* __restrict__ w3,
                        const float* __restrict__ b3, float* __restrict__ out) {
    __shared__ float h1s[32][256];
    __shared__ float h2s[32][32];
    int t = threadIdx.x;
    for (int idx = t; idx < 32 * 256; idx += 1024) {
        float v = h1g[idx] + b1[idx & 255];
        h1s[idx >> 8][idx & 255] = (v >= 0.f) ? v : 0.2f * v;
    }
    __syncthreads();
    {
        int b = t >> 5, o = t & 31;
        float s = 0.f;
#pragma unroll 8
        for (int k = 0; k < 256; k++) s += h1s[b][k] * w2[o * 256 + k];
        s += b2[o];
        h2s[b][o] = (s >= 0.f) ? s : 0.2f * s;
    }
    __syncthreads();
    if (t < 64) {
        int b = t >> 1, o = t & 1;
        float s = 0.f;
#pragma unroll
        for (int k = 0; k < 32; k++) s += h2s[b][k] * w3[o * 32 + k];
        out[b * 2 + o] = s + b3[o];
    }
}

// ---------------------------------------------------------------------------
// Launch
// ---------------------------------------------------------------------------
extern "C" void kernel_launch(void* const* d_in, const int* in_sizes, int n_in,
                              void* d_out, int out_size) {
    const float* x    = (const float*)d_in[0];
    const float* t    = (const float*)d_in[1];
    const float* gu   = (const float*)d_in[2];
    const int*   ei   = (const int*)d_in[3];
    const float* w1   = (const float*)d_in[4];
    const float* b1   = (const float*)d_in[5];
    const float* w2   = (const float*)d_in[6];
    const float* b2   = (const float*)d_in[7];
    const float* fcw  = (const float*)d_in[8];
    const float* fcb  = (const float*)d_in[9];
    const float* f1w  = (const float*)d_in[10];
    const float* f1b  = (const float*)d_in[11];
    const float* f2w  = (const float*)d_in[12];
    const float* f2b  = (const float*)d_in[13];
    const float* f3w  = (const float*)d_in[14];
    const float* f3b  = (const float*)d_in[15];
    float* out = (float*)d_out;

    const int* rowp = ei;
    const int* colp = ei + kE;

    float* base = nullptr;
    cudaGetSymbolAddress((void**)&base, g_scratch);
    float* p_lslr = base + OFF_LSLR;
    float* p_A    = base + OFF_A;
    float* p_disD = base + OFF_DISD;
    float* p_xw1  = base + OFF_XW1;
    float* p_h    = base + OFF_H;
    float* p_xw2  = base + OFF_XW2;
    float* p_emb  = base + OFF_EMB;
    float* p_disS = base + OFF_DISS;
    int*   p_degS = (int*)(base + OFF_DEGS);
    float* p_xws1 = base + OFF_XWS1;
    float* p_sc1  = base + OFF_SC1;
    float* p_xws2 = base + OFF_XWS2;
    float* p_h1   = base + OFF_H1;
    float* p_degD = base + OFF_DEGD;

    // init
    k_zero<<<64, 256>>>(p_degS, p_h1, p_degD);

    // Gumbel adjacency
    k_lslr<<<kNTOT / 8, 256>>>(t, fcw, p_lslr);
    k_buildA<<<kBZ * kN * kN / 256, 256>>>(gu, fcb, p_lslr, p_A);
    k_colsum_part<<<dim3(kBZ, 8), kN>>>(p_A, p_degD);
    k_rsqrtD<<<kNTOT / 256, 256>>>(p_degD, p_disD);

    // sparse degrees
    k_degS<<<kE / 256, 256>>>(colp, p_degS);
    k_disS<<<kNTOT / 256, 256>>>(p_degS, p_disS);

    // dense GCN layer 1
    k_gemm128<false><<<dim3(kF1 / 128, kN / 128, kBZ), 256>>>(
        x, (long)kN * kN, w1, p_xw1, (long)kN * kF1, kF1, kN);
    k_prop128<true><<<dim3(kF1 / 128, kN / 128, kBZ), 256>>>(
        p_A, p_xw1, p_disD, b1, p_h, kF1, kF1, 0);

    // dense GCN layer 2 -> emb[:, 0:128]
    k_gemm128<false><<<dim3(kF2 / 128, kN / 128, kBZ), 256>>>(
        p_h, (long)kN * kF1, w2, p_xw2, (long)kN * kF2, kF2, kF1);
    k_prop128<false><<<dim3(kF2 / 128, kN / 128, kBZ), 256>>>(
        p_A, p_xw2, p_disD, b2, p_emb, kF2, 256, 0);

    // sparse GCN layer 1
    k_gemm128<false><<<dim3(kF1 / 128, kNTOT / 128, 1), 256>>>(
        x, 0, w1, p_xws1, 0, kF1, kN);
    k_init_sc<<<kNTOT * kF1 / 256, 256>>>(p_xws1, p_disS, b1, p_sc1, kF1, kF1, 0, 8);
    k_scatter<6><<<kE * (kF1 / 4) / 256, 256>>>(rowp, colp, p_xws1, p_disS,
                                                p_sc1, kF1, kF1, 0);

    // sparse GCN layer 2 -> emb[:, 128:256]
    k_gemm128<true><<<dim3(kF2 / 128, kNTOT / 128, 1), 256>>>(
        p_sc1, 0, w2, p_xws2, 0, kF2, kF1);
    k_init_sc<<<kNTOT * kF2 / 256, 256>>>(p_xws2, p_disS, b2, p_emb, kF2, 256, 128, 7);
    k_scatter<5><<<kE * (kF2 / 4) / 256, 256>>>(rowp, colp, p_xws2, p_disS,
                                                p_emb, kF2, 256, 128);

    // MLP head
    k_fcn1<<<dim3(256 / 64, 128), 256>>>(p_emb, f1w, p_h1);
    k_fcn23<<<1, 1024>>>(p_h1, f1b, f2w, f2b, f3w, f3b, out);
}

// round 3
// speedup vs baseline: 1.5115x; 1.3851x over previous
#include <cuda_runtime.h>
#include <cstdint>

// ---------------------------------------------------------------------------
// Problem constants
// ---------------------------------------------------------------------------
constexpr int kN    = 512;
constexpr int kBZ   = 32;
constexpr int kTC   = 256;
constexpr int kF1   = 256;
constexpr int kF2   = 128;
constexpr int kE    = 524288;
constexpr int kNTOT = kBZ * kN;          // 16384
constexpr int kKTOT = kF2 * 2 * kN;      // 131072

// ---------------------------------------------------------------------------
// Scratch
// ---------------------------------------------------------------------------
constexpr long OFF_LSLR = 0;
constexpr long OFF_A    = OFF_LSLR + (long)kNTOT * 4;
constexpr long OFF_DISD = OFF_A    + (long)kBZ * kN * kN;
constexpr long OFF_XW1  = OFF_DISD + (long)kBZ * kN;
constexpr long OFF_H    = OFF_XW1  + (long)kBZ * kN * kF1;
constexpr long OFF_XW2  = OFF_H    + (long)kBZ * kN * kF1;
constexpr long OFF_EMB  = OFF_XW2  + (long)kBZ * kN * kF2;
constexpr long OFF_DISS = OFF_EMB  + (long)kNTOT * 256;
constexpr long OFF_DEGS = OFF_DISS + (long)kNTOT;
constexpr long OFF_XWS1 = OFF_DEGS + (long)kNTOT;
constexpr long OFF_SC1  = OFF_XWS1 + (long)kNTOT * kF1;
constexpr long OFF_XWS2 = OFF_SC1  + (long)kNTOT * kF1;
constexpr long OFF_H1   = OFF_XWS2 + (long)kNTOT * kF2;
constexpr long OFF_DEGD = OFF_H1   + (long)kBZ * 256;
constexpr long SCRATCH_FLOATS = OFF_DEGD + (long)kNTOT;

__device__ __align__(16) float g_scratch[SCRATCH_FLOATS];

// ---------------------------------------------------------------------------
// tf32 helpers
// ---------------------------------------------------------------------------
__device__ __forceinline__ uint32_t f2tf(float x) {
    uint32_t r;
    asm("cvt.rna.tf32.f32 %0, %1;" : "=r"(r) : "f"(x));
    return r;
}
__device__ __forceinline__ void mma_tf32(float* d, const uint32_t* a,
                                         uint32_t b0, uint32_t b1) {
    asm volatile(
        "mma.sync.aligned.m16n8k8.row.col.f32.tf32.tf32.f32 "
        "{%0,%1,%2,%3},{%4,%5,%6,%7},{%8,%9},{%0,%1,%2,%3};"
        : "+f"(d[0]), "+f"(d[1]), "+f"(d[2]), "+f"(d[3])
        : "r"(a[0]), "r"(a[1]), "r"(a[2]), "r"(a[3]), "r"(b0), "r"(b1));
}

// ---------------------------------------------------------------------------
// Small kernels (unchanged, proven)
// ---------------------------------------------------------------------------
__global__ void k_zero(int* degS, float* h1, float* degD) {
    int i = blockIdx.x * 256 + threadIdx.x;
    if (i < kNTOT) { degS[i] = 0; degD[i] = 1.f; }
    if (i < kBZ * 256) h1[i] = 0.f;
}

__global__ void k_lslr(const float* __restrict__ t, const float* __restrict__ fcw,
                       float* __restrict__ lslr) {
    int warp = (blockIdx.x * blockDim.x + threadIdx.x) >> 5;
    int lane = threadIdx.x & 31;
    if (warp >= kNTOT) return;
    const float* tn = t + (long)warp * kTC;
    const float* w0 = fcw;
    const float* w1 = fcw + 512;
    float s0 = 0.f, s1 = 0.f, r0 = 0.f, r1 = 0.f;
#pragma unroll
    for (int q = 0; q < 8; q++) {
        int d = lane + 32 * q;
        float u = fmaxf(tn[d], 0.f);
        s0 += u * w0[d];       s1 += u * w1[d];
        r0 += u * w0[256 + d]; r1 += u * w1[256 + d];
    }
#pragma unroll
    for (int off = 16; off; off >>= 1) {
        s0 += __shfl_down_sync(0xffffffffu, s0, off);
        s1 += __shfl_down_sync(0xffffffffu, s1, off);
        r0 += __shfl_down_sync(0xffffffffu, r0, off);
        r1 += __shfl_down_sync(0xffffffffu, r1, off);
    }
    if (lane == 0)
        reinterpret_cast<float4*>(lslr)[warp] = make_float4(s0, s1, r0, r1);
}

__global__ void k_buildA(const float* __restrict__ gu, const float* __restrict__ fcb,
                         const float* __restrict__ lslr, float* __restrict__ A) {
    int idx = blockIdx.x * 256 + threadIdx.x;
    int j = idx & 511;
    int i = (idx >> 9) & 511;
    int b = idx >> 18;
    float2 u = reinterpret_cast<const float2*>(gu)[idx];
    float ux = fminf(fmaxf(u.x, 1e-9f), 1.0f - 1e-9f);
    float uy = fminf(fmaxf(u.y, 1e-9f), 1.0f - 1e-9f);
    float g0 = -logf(-logf(ux));
    float g1 = -logf(-logf(uy));
    float4 sj = reinterpret_cast<const float4*>(lslr)[b * kN + j];
    float4 si = reinterpret_cast<const float4*>(lslr)[b * kN + i];
    float y0 = si.z + sj.x + fcb[0] + g0;
    float y1 = si.w + sj.y + fcb[1] + g1;
    A[idx] = (y0 >= y1) ? 1.f : 0.f;
}

__global__ void k_colsum_part(const float* __restrict__ A, float* __restrict__ degD) {
    int b = blockIdx.x;
    int j = threadIdx.x;
    int r0 = blockIdx.y * 64;
    const float* Ab = A + (long)b * kN * kN;
    float s = 0.f;
#pragma unroll 8
    for (int r = r0; r < r0 + 64; r++) s += Ab[(long)r * kN + j];
    atomicAdd(&degD[b * kN + j], s);
}

__global__ void k_rsqrtD(const float* __restrict__ degD, float* __restrict__ disD) {
    int i = blockIdx.x * 256 + threadIdx.x;
    if (i < kNTOT) disD[i] = rsqrtf(degD[i]);
}

__global__ void k_degS(const int* __restrict__ colp, int* degS) {
    int e = blockIdx.x * 256 + threadIdx.x;
    if (e < kE) atomicAdd(&degS[colp[e]], 1);
}

__global__ void k_disS(const int* __restrict__ degS, float* __restrict__ disS) {
    int n = blockIdx.x * 256 + threadIdx.x;
    if (n < kNTOT) disS[n] = rsqrtf((float)degS[n] + 1.f);
}

// ---------------------------------------------------------------------------
// tf32 NT GEMM: C[M x Nf] = A[M x K] @ B[Nf x K]^T  (fp32 accum)
// BM=BN=128, BK=16, 256 thr, 8 warps (4m x 2n), warp tile 32x64.
// SMEM m-major pad 20 (conflict-free fragment loads).
// ---------------------------------------------------------------------------
template <bool RELU_A>
__global__ __launch_bounds__(256) void k_gemm_tf32(
        const float* __restrict__ A, long aStride,
        const float* __restrict__ B,
        float* __restrict__ C, long cStride,
        int Nf, int K) {
    __shared__ uint32_t As[2][128][20];
    __shared__ uint32_t Bs[2][128][20];
    const float* Ab = A + (long)blockIdx.z * aStride;
    float* Cb = C + (long)blockIdx.z * cStride;
    int m0 = blockIdx.y * 128, n0 = blockIdx.x * 128;
    int t = threadIdx.x;
    int wid = t >> 5, lane = t & 31;
    int mw = (wid >> 1) * 32, nw = (wid & 1) * 64;
    int g = lane >> 2, tg = lane & 3;
    int lr = t >> 2, lc = (t & 3) << 2;   // loader: rows lr, lr+64; cols lc..lc+3

    float acc[2][8][4];
#pragma unroll
    for (int i = 0; i < 2; i++)
#pragma unroll
        for (int j = 0; j < 8; j++)
#pragma unroll
            for (int c = 0; c < 4; c++) acc[i][j][c] = 0.f;

    const float* aP0 = Ab + (long)(m0 + lr) * K + lc;
    const float* aP1 = Ab + (long)(m0 + lr + 64) * K + lc;
    const float* bP0 = B + (long)(n0 + lr) * K + lc;
    const float* bP1 = B + (long)(n0 + lr + 64) * K + lc;

    auto cvt4 = [](float4 v, bool relu) -> uint4 {
        if (relu) {
            v.x = fmaxf(v.x, 0.f); v.y = fmaxf(v.y, 0.f);
            v.z = fmaxf(v.z, 0.f); v.w = fmaxf(v.w, 0.f);
        }
        uint4 r;
        r.x = f2tf(v.x); r.y = f2tf(v.y); r.z = f2tf(v.z); r.w = f2tf(v.w);
        return r;
    };

    // prefetch tile 0
    {
        uint4 a0 = cvt4(*reinterpret_cast<const float4*>(aP0), RELU_A);
        uint4 a1 = cvt4(*reinterpret_cast<const float4*>(aP1), RELU_A);
        uint4 b0 = cvt4(*reinterpret_cast<const float4*>(bP0), false);
        uint4 b1 = cvt4(*reinterpret_cast<const float4*>(bP1), false);
        *reinterpret_cast<uint4*>(&As[0][lr][lc]) = a0;
        *reinterpret_cast<uint4*>(&As[0][lr + 64][lc]) = a1;
        *reinterpret_cast<uint4*>(&Bs[0][lr][lc]) = b0;
        *reinterpret_cast<uint4*>(&Bs[0][lr + 64][lc]) = b1;
    }
    __syncthreads();

    int buf = 0;
    for (int k0 = 0; k0 < K; k0 += 16) {
        bool more = (k0 + 16) < K;
        float4 na0, na1, nb0, nb1;
        if (more) {
            na0 = *reinterpret_cast<const float4*>(aP0 + k0 + 16);
            na1 = *reinterpret_cast<const float4*>(aP1 + k0 + 16);
            nb0 = *reinterpret_cast<const float4*>(bP0 + k0 + 16);
            nb1 = *reinterpret_cast<const float4*>(bP1 + k0 + 16);
        }
#pragma unroll
        for (int s = 0; s < 2; s++) {
            int kk = s * 8 + tg;
            uint32_t af[2][4];
#pragma unroll
            for (int mt = 0; mt < 2; mt++) {
                int r = mw + mt * 16 + g;
                af[mt][0] = As[buf][r][kk];
                af[mt][1] = As[buf][r + 8][kk];
                af[mt][2] = As[buf][r][kk + 4];
                af[mt][3] = As[buf][r + 8][kk + 4];
            }
#pragma unroll
            for (int j = 0; j < 8; j++) {
                int nr = nw + j * 8 + g;
                uint32_t b0 = Bs[buf][nr][kk];
                uint32_t b1 = Bs[buf][nr][kk + 4];
                mma_tf32(acc[0][j], af[0], b0, b1);
                mma_tf32(acc[1][j], af[1], b0, b1);
            }
        }
        if (more) {
            int nb = buf ^ 1;
            *reinterpret_cast<uint4*>(&As[nb][lr][lc]) = cvt4(na0, RELU_A);
            *reinterpret_cast<uint4*>(&As[nb][lr + 64][lc]) = cvt4(na1, RELU_A);
            *reinterpret_cast<uint4*>(&Bs[nb][lr][lc]) = cvt4(nb0, false);
            *reinterpret_cast<uint4*>(&Bs[nb][lr + 64][lc]) = cvt4(nb1, false);
            __syncthreads();
            buf = nb;
        }
    }

#pragma unroll
    for (int mt = 0; mt < 2; mt++) {
        int row = m0 + mw + mt * 16 + g;
#pragma unroll
        for (int j = 0; j < 8; j++) {
            int col = n0 + nw + j * 8 + 2 * tg;
            *reinterpret_cast<float2*>(Cb + (long)row * Nf + col) =
                make_float2(acc[mt][j][0], acc[mt][j][1]);
            *reinterpret_cast<float2*>(Cb + (long)(row + 8) * Nf + col) =
                make_float2(acc[mt][j][2], acc[mt][j][3]);
        }
    }
}

// ---------------------------------------------------------------------------
// tf32 dense GCN propagation:
//   out[i][f] = di*( sum_j Adj[j][i]*dj*XW[j][f] + di*XW[i][f] ) + bias[f]
// m=i, n=f, k=j. Both operands k-major in SMEM (pad 136) — no transposes.
// Adjacency is exact in tf32 (0/1).
// ---------------------------------------------------------------------------
template <bool RELU>
__global__ __launch_bounds__(256) void k_prop_tf32(
        const float* __restrict__ Adj, const float* __restrict__ XW,
        const float* __restrict__ dis, const float* __restrict__ bias,
        float* __restrict__ out, int F, int outStride, int outOffset) {
    __shared__ uint32_t As[2][16][136];   // Adj[j][i] tile
    __shared__ uint32_t Bs[2][16][136];   // dj*XW[j][f] tile
    int b = blockIdx.z;
    const float* Ab = Adj + (long)b * kN * kN;
    const float* Xb = XW + (long)b * kN * F;
    const float* db = dis + b * kN;
    float* Ob = out + (long)b * kN * outStride + outOffset;
    int i0 = blockIdx.y * 128, f0 = blockIdx.x * 128;
    int t = threadIdx.x;
    int wid = t >> 5, lane = t & 31;
    int mw = (wid >> 1) * 32, nw = (wid & 1) * 64;
    int g = lane >> 2, tg = lane & 3;
    int jj = t >> 4;               // 0..15 (k row)
    int ii = (t & 15) << 3;        // 0..120 (two float4s: ii, ii+4)

    float acc[2][8][4];
#pragma unroll
    for (int i = 0; i < 2; i++)
#pragma unroll
        for (int j = 0; j < 8; j++)
#pragma unroll
            for (int c = 0; c < 4; c++) acc[i][j][c] = 0.f;

    auto stTile = [&](int bufI, float4 a0, float4 a1, float4 x0, float4 x1, float dj) {
        uint4 ua0, ua1, ux0, ux1;
        ua0.x = f2tf(a0.x); ua0.y = f2tf(a0.y); ua0.z = f2tf(a0.z); ua0.w = f2tf(a0.w);
        ua1.x = f2tf(a1.x); ua1.y = f2tf(a1.y); ua1.z = f2tf(a1.z); ua1.w = f2tf(a1.w);
        ux0.x = f2tf(x0.x * dj); ux0.y = f2tf(x0.y * dj);
        ux0.z = f2tf(x0.z * dj); ux0.w = f2tf(x0.w * dj);
        ux1.x = f2tf(x1.x * dj); ux1.y = f2tf(x1.y * dj);
        ux1.z = f2tf(x1.z * dj); ux1.w = f2tf(x1.w * dj);
        *reinterpret_cast<uint4*>(&As[bufI][jj][ii]) = ua0;
        *reinterpret_cast<uint4*>(&As[bufI][jj][ii + 4]) = ua1;
        *reinterpret_cast<uint4*>(&Bs[bufI][jj][ii]) = ux0;
        *reinterpret_cast<uint4*>(&Bs[bufI][jj][ii + 4]) = ux1;
    };

    // prefetch tile 0
    {
        const float* ap = Ab + (long)jj * kN + i0 + ii;
        const float* xp = Xb + (long)jj * F + f0 + ii;
        stTile(0,
               *reinterpret_cast<const float4*>(ap),
               *reinterpret_cast<const float4*>(ap + 4),
               *reinterpret_cast<const float4*>(xp),
               *reinterpret_cast<const float4*>(xp + 4),
               db[jj]);
    }
    __syncthreads();

    int buf = 0;
    for (int j0 = 0; j0 < kN; j0 += 16) {
        bool more = (j0 + 16) < kN;
        float4 na0, na1, nx0, nx1;
        float djn = 0.f;
        if (more) {
            const float* ap = Ab + (long)(j0 + 16 + jj) * kN + i0 + ii;
            const float* xp = Xb + (long)(j0 + 16 + jj) * F + f0 + ii;
            na0 = *reinterpret_cast<const float4*>(ap);
            na1 = *reinterpret_cast<const float4*>(ap + 4);
            nx0 = *reinterpret_cast<const float4*>(xp);
            nx1 = *reinterpret_cast<const float4*>(xp + 4);
            djn = db[j0 + 16 + jj];
        }
#pragma unroll
        for (int s = 0; s < 2; s++) {
            int kk = s * 8 + tg;
            uint32_t af[2][4];
#pragma unroll
            for (int mt = 0; mt < 2; mt++) {
                int m = mw + mt * 16 + g;
                af[mt][0] = As[buf][kk][m];
                af[mt][1] = As[buf][kk][m + 8];
                af[mt][2] = As[buf][kk + 4][m];
                af[mt][3] = As[buf][kk + 4][m + 8];
            }
#pragma unroll
            for (int j = 0; j < 8; j++) {
                int n = nw + j * 8 + g;
                uint32_t b0 = Bs[buf][kk][n];
                uint32_t b1 = Bs[buf][kk + 4][n];
                mma_tf32(acc[0][j], af[0], b0, b1);
                mma_tf32(acc[1][j], af[1], b0, b1);
            }
        }
        if (more) {
            int nb = buf ^ 1;
            stTile(nb, na0, na1, nx0, nx1, djn);
            __syncthreads();
            buf = nb;
        }
    }

#pragma unroll
    for (int mt = 0; mt < 2; mt++) {
        int rowA = i0 + mw + mt * 16 + g;
        float diA = db[rowA], diB = db[rowA + 8];
#pragma unroll
        for (int j = 0; j < 8; j++) {
            int col = f0 + nw + j * 8 + 2 * tg;
            float2 bb = *reinterpret_cast<const float2*>(bias + col);
            float2 xA = *reinterpret_cast<const float2*>(Xb + (long)rowA * F + col);
            float2 xB = *reinterpret_cast<const float2*>(Xb + (long)(rowA + 8) * F + col);
            float v0 = diA * (acc[mt][j][0] + diA * xA.x) + bb.x;
            float v1 = diA * (acc[mt][j][1] + diA * xA.y) + bb.y;
            float v2 = diB * (acc[mt][j][2] + diB * xB.x) + bb.x;
            float v3 = diB * (acc[mt][j][3] + diB * xB.y) + bb.y;
            if (RELU) {
                v0 = fmaxf(v0, 0.f); v1 = fmaxf(v1, 0.f);
                v2 = fmaxf(v2, 0.f); v3 = fmaxf(v3, 0.f);
            }
            *reinterpret_cast<float2*>(Ob + (long)rowA * outStride + col) =
                make_float2(v0, v1);
            *reinterpret_cast<float2*>(Ob + (long)(rowA + 8) * outStride + col) =
                make_float2(v2, v3);
        }
    }
}

// ---------------------------------------------------------------------------
// Sparse GCN helpers (unchanged)
// ---------------------------------------------------------------------------
__global__ void k_init_sc(const float* __restrict__ xw, const float* __restrict__ disS,
                          const float* __restrict__ bias, float* __restrict__ out,
                          int F, int outStride, int outOffset, int logF) {
    int idx = blockIdx.x * 256 + threadIdx.x;
    int n = idx >> logF;
    int f = idx & (F - 1);
    float d = disS[n];
    out[(long)n * outStride + outOffset + f] = xw[idx] * d * d + bias[f];
}

template <int LOGFQ>
__global__ void k_scatter(const int* __restrict__ rowp, const int* __restrict__ colp,
                          const float* __restrict__ xw, const float* __restrict__ disS,
                          float* __restrict__ out, int F, int outStride, int outOffset) {
    int idx = blockIdx.x * 256 + threadIdx.x;
    int e = idx >> LOGFQ;
    int q = (idx & ((1 << LOGFQ) - 1)) << 2;
    int r = rowp[e], c = colp[e];
    float s = disS[r] * disS[c];
    float4 v = *reinterpret_cast<const float4*>(xw + (long)r * F + q);
    v.x *= s; v.y *= s; v.z *= s; v.w *= s;
    atomicAdd(reinterpret_cast<float4*>(out + (long)c * outStride + outOffset + q), v);
}

// ---------------------------------------------------------------------------
// fcn1 split-K (bandwidth-bound) + head (unchanged)
// ---------------------------------------------------------------------------
__global__ void k_fcn1(const float* __restrict__ emb, const float* __restrict__ W,
                       float* __restrict__ h1) {
    constexpr int KC = kKTOT / 128;
    __shared__ float As[16][32];
    __shared__ float Bs[16][64];
    int n0 = blockIdx.x * 64;
    int kbase = blockIdx.y * KC;
    int t = threadIdx.x;
    int m = t & 31;
    int nb = (t >> 5) << 3;
    float acc[8];
#pragma unroll
    for (int j = 0; j < 8; j++) acc[j] = 0.f;

    for (int k0 = kbase; k0 < kbase + KC; k0 += 16) {
        if (t < 128) {
            int row = t >> 2, c4 = (t & 3) << 2;
            float4 a = *reinterpret_cast<const float4*>(emb + (long)row * kKTOT + k0 + c4);
            As[c4 + 0][row] = a.x; As[c4 + 1][row] = a.y;
            As[c4 + 2][row] = a.z; As[c4 + 3][row] = a.w;
        }
        {
            int row = t >> 2, c4 = (t & 3) << 2;
            float4 b = *reinterpret_cast<const float4*>(W + (long)(n0 + row) * kKTOT + k0 + c4);
            Bs[c4 + 0][row] = b.x; Bs[c4 + 1][row] = b.y;
            Bs[c4 + 2][row] = b.z; Bs[c4 + 3][row] = b.w;
        }
        __syncthreads();
#pragma unroll
        for (int k = 0; k < 16; k++) {
            float a = As[k][m];
#pragma unroll
            for (int j = 0; j < 8; j++) acc[j] += a * Bs[k][nb + j];
        }
        __syncthreads();
    }
#pragma unroll
    for (int j = 0; j < 8; j++)
        atomicAdd(&h1[m * 256 + n0 + nb + j], acc[j]);
}

__global__ void k_fcn23(const float* __restrict__ h1g,
                        const float* __restrict__ b1, const float* __restrict__ w2,
                        const float* __restrict__ b2, const float* __restrict__ w3,
                        const float* __restrict__ b3, float* __restrict__ out) {
    __shared__ float h1s[32][256];
    __shared__ float h2s[32][32];
    int t = threadIdx.x;
    for (int idx = t; idx < 32 * 256; idx += 1024) {
        float v = h1g[idx] + b1[idx & 255];
        h1s[idx >> 8][idx & 255] = (v >= 0.f) ? v : 0.2f * v;
    }
    __syncthreads();
    {
        int b = t >> 5, o = t & 31;
        float s = 0.f;
#pragma unroll 8
        for (int k = 0; k < 256; k++) s += h1s[b][k] * w2[o * 256 + k];
        s += b2[o];
        h2s[b][o] = (s >= 0.f) ? s : 0.2f * s;
    }
    __syncthreads();
    if (t < 64) {
        int b = t >> 1, o = t & 1;
        float s = 0.f;
#pragma unroll
        for (int k = 0; k < 32; k++) s += h2s[b][k] * w3[o * 32 + k];
        out[b * 2 + o] = s + b3[o];
    }
}

// ---------------------------------------------------------------------------
// Launch
// ---------------------------------------------------------------------------
extern "C" void kernel_launch(void* const* d_in, const int* in_sizes, int n_in,
                              void* d_out, int out_size) {
    const float* x    = (const float*)d_in[0];
    const float* t    = (const float*)d_in[1];
    const float* gu   = (const float*)d_in[2];
    const int*   ei   = (const int*)d_in[3];
    const float* w1   = (const float*)d_in[4];
    const float* b1   = (const float*)d_in[5];
    const float* w2   = (const float*)d_in[6];
    const float* b2   = (const float*)d_in[7];
    const float* fcw  = (const float*)d_in[8];
    const float* fcb  = (const float*)d_in[9];
    const float* f1w  = (const float*)d_in[10];
    const float* f1b  = (const float*)d_in[11];
    const float* f2w  = (const float*)d_in[12];
    const float* f2b  = (const float*)d_in[13];
    const float* f3w  = (const float*)d_in[14];
    const float* f3b  = (const float*)d_in[15];
    float* out = (float*)d_out;

    const int* rowp = ei;
    const int* colp = ei + kE;

    float* base = nullptr;
    cudaGetSymbolAddress((void**)&base, g_scratch);
    float* p_lslr = base + OFF_LSLR;
    float* p_A    = base + OFF_A;
    float* p_disD = base + OFF_DISD;
    float* p_xw1  = base + OFF_XW1;
    float* p_h    = base + OFF_H;
    float* p_xw2  = base + OFF_XW2;
    float* p_emb  = base + OFF_EMB;
    float* p_disS = base + OFF_DISS;
    int*   p_degS = (int*)(base + OFF_DEGS);
    float* p_xws1 = base + OFF_XWS1;
    float* p_sc1  = base + OFF_SC1;
    float* p_xws2 = base + OFF_XWS2;
    float* p_h1   = base + OFF_H1;
    float* p_degD = base + OFF_DEGD;

    k_zero<<<64, 256>>>(p_degS, p_h1, p_degD);

    // Gumbel adjacency
    k_lslr<<<kNTOT / 8, 256>>>(t, fcw, p_lslr);
    k_buildA<<<kBZ * kN * kN / 256, 256>>>(gu, fcb, p_lslr, p_A);
    k_colsum_part<<<dim3(kBZ, 8), kN>>>(p_A, p_degD);
    k_rsqrtD<<<kNTOT / 256, 256>>>(p_degD, p_disD);

    // sparse degrees
    k_degS<<<kE / 256, 256>>>(colp, p_degS);
    k_disS<<<kNTOT / 256, 256>>>(p_degS, p_disS);

    // dense GCN layer 1 (tf32 tensor cores)
    k_gemm_tf32<false><<<dim3(kF1 / 128, kN / 128, kBZ), 256>>>(
        x, (long)kN * kN, w1, p_xw1, (long)kN * kF1, kF1, kN);
    k_prop_tf32<true><<<dim3(kF1 / 128, kN / 128, kBZ), 256>>>(
        p_A, p_xw1, p_disD, b1, p_h, kF1, kF1, 0);

    // dense GCN layer 2 -> emb[:, 0:128]
    k_gemm_tf32<false><<<dim3(kF2 / 128, kN / 128, kBZ), 256>>>(
        p_h, (long)kN * kF1, w2, p_xw2, (long)kN * kF2, kF2, kF1);
    k_prop_tf32<false><<<dim3(kF2 / 128, kN / 128, kBZ), 256>>>(
        p_A, p_xw2, p_disD, b2, p_emb, kF2, 256, 0);

    // sparse GCN layer 1
    k_gemm_tf32<false><<<dim3(kF1 / 128, kNTOT / 128, 1), 256>>>(
        x, 0, w1, p_xws1, 0, kF1, kN);
    k_init_sc<<<kNTOT * kF1 / 256, 256>>>(p_xws1, p_disS, b1, p_sc1, kF1, kF1, 0, 8);
    k_scatter<6><<<kE * (kF1 / 4) / 256, 256>>>(rowp, colp, p_xws1, p_disS,
                                                p_sc1, kF1, kF1, 0);

    // sparse GCN layer 2 -> emb[:, 128:256]
    k_gemm_tf32<true><<<dim3(kF2 / 128, kNTOT / 128, 1), 256>>>(
        p_sc1, 0, w2, p_xws2, 0, kF2, kF1);
    k_init_sc<<<kNTOT * kF2 / 256, 256>>>(p_xws2, p_disS, b2, p_emb, kF2, 256, 128, 7);
    k_scatter<5><<<kE * (kF2 / 4) / 256, 256>>>(rowp, colp, p_xws2, p_disS,
                                                p_emb, kF2, 256, 128);

    // MLP head (fp32)
    k_fcn1<<<dim3(256 / 64, 128), 256>>>(p_emb, f1w, p_h1);
    k_fcn23<<<1, 1024>>>(p_h1, f1b, f2w, f2b, f3w, f3b, out);
}

// round 4
// speedup vs baseline: 1.7984x; 1.1898x over previous
#include <cuda_runtime.h>
#include <cstdint>

// ---------------------------------------------------------------------------
// Problem constants
// ---------------------------------------------------------------------------
constexpr int kN    = 512;
constexpr int kBZ   = 32;
constexpr int kTC   = 256;
constexpr int kF1   = 256;
constexpr int kF2   = 128;
constexpr int kE    = 524288;
constexpr int kNTOT = kBZ * kN;          // 16384
constexpr int kKTOT = kF2 * 2 * kN;      // 131072

// ---------------------------------------------------------------------------
// Scratch (offsets in floats)
// ---------------------------------------------------------------------------
constexpr long OFF_LSLR = 0;
constexpr long OFF_A8   = OFF_LSLR + (long)kNTOT * 4;            // u8 view
constexpr long OFF_DISD = OFF_A8   + (long)kBZ * kN * kN / 4;
constexpr long OFF_XW1  = OFF_DISD + (long)kNTOT;
constexpr long OFF_H    = OFF_XW1  + (long)kNTOT * kF1;
constexpr long OFF_XW2  = OFF_H    + (long)kNTOT * kF1;
constexpr long OFF_EMB  = OFF_XW2  + (long)kNTOT * kF2;
constexpr long OFF_DISS = OFF_EMB  + (long)kNTOT * 256;
constexpr long OFF_DEGS = OFF_DISS + (long)kNTOT;                // int
constexpr long OFF_XWS1 = OFF_DEGS + (long)kNTOT;
constexpr long OFF_SC1  = OFF_XWS1 + (long)kNTOT * kF1;
constexpr long OFF_XWS2 = OFF_SC1  + (long)kNTOT * kF1;
constexpr long OFF_H1   = OFF_XWS2 + (long)kNTOT * kF2;
constexpr long OFF_DEGD = OFF_H1   + (long)kBZ * 256;
constexpr long OFF_NS   = OFF_DEGD + (long)kNTOT;                // int, kNTOT+1
constexpr long OFF_CUR  = OFF_NS   + (long)kNTOT + 4;            // int
constexpr long OFF_ESRC = OFF_CUR  + (long)kNTOT;                // int, kE
constexpr long SCRATCH_FLOATS = OFF_ESRC + (long)kE;

__device__ __align__(16) float g_scratch[SCRATCH_FLOATS];

// ---------------------------------------------------------------------------
// tf32 helpers
// ---------------------------------------------------------------------------
__device__ __forceinline__ uint32_t f2tf(float x) {
    uint32_t r;
    asm("cvt.rna.tf32.f32 %0, %1;" : "=r"(r) : "f"(x));
    return r;
}
__device__ __forceinline__ void mma_tf32(float* d, const uint32_t* a,
                                         uint32_t b0, uint32_t b1) {
    asm volatile(
        "mma.sync.aligned.m16n8k8.row.col.f32.tf32.tf32.f32 "
        "{%0,%1,%2,%3},{%4,%5,%6,%7},{%8,%9},{%0,%1,%2,%3};"
        : "+f"(d[0]), "+f"(d[1]), "+f"(d[2]), "+f"(d[3])
        : "r"(a[0]), "r"(a[1]), "r"(a[2]), "r"(a[3]), "r"(b0), "r"(b1));
}

// ---------------------------------------------------------------------------
// Small kernels
// ---------------------------------------------------------------------------
__global__ void k_zero(int* degS, float* h1, float* degD) {
    int i = blockIdx.x * 256 + threadIdx.x;
    if (i < kNTOT) { degS[i] = 0; degD[i] = 1.f; }
    if (i < kBZ * 256) h1[i] = 0.f;
}

__global__ void k_lslr(const float* __restrict__ t, const float* __restrict__ fcw,
                       float* __restrict__ lslr) {
    int warp = (blockIdx.x * blockDim.x + threadIdx.x) >> 5;
    int lane = threadIdx.x & 31;
    if (warp >= kNTOT) return;
    const float* tn = t + (long)warp * kTC;
    const float* w0 = fcw;
    const float* w1 = fcw + 512;
    float s0 = 0.f, s1 = 0.f, r0 = 0.f, r1 = 0.f;
#pragma unroll
    for (int q = 0; q < 8; q++) {
        int d = lane + 32 * q;
        float u = fmaxf(tn[d], 0.f);
        s0 += u * w0[d];       s1 += u * w1[d];
        r0 += u * w0[256 + d]; r1 += u * w1[256 + d];
    }
#pragma unroll
    for (int off = 16; off; off >>= 1) {
        s0 += __shfl_down_sync(0xffffffffu, s0, off);
        s1 += __shfl_down_sync(0xffffffffu, s1, off);
        r0 += __shfl_down_sync(0xffffffffu, r0, off);
        r1 += __shfl_down_sync(0xffffffffu, r1, off);
    }
    if (lane == 0)
        reinterpret_cast<float4*>(lslr)[warp] = make_float4(s0, s1, r0, r1);
}

// A8[b][i][j] = (y0 >= y1) ? 1 : 0  — 4 j per thread, uchar4 store
__global__ void k_buildA(const float* __restrict__ gu, const float* __restrict__ fcb,
                         const float* __restrict__ lslr, unsigned char* __restrict__ A8) {
    int idx = blockIdx.x * 256 + threadIdx.x;      // 2,097,152
    int j0 = (idx & 127) << 2;
    int i  = (idx >> 7) & 511;
    int b  = idx >> 16;
    const float4* l4 = reinterpret_cast<const float4*>(lslr) + b * kN;
    const float4* g4 = reinterpret_cast<const float4*>(
        gu + ((long)(b * kN + i) * kN + j0) * 2);
    float4 u01 = g4[0];   // j0:(x,y) j0+1:(z,w)
    float4 u23 = g4[1];
    float4 si = l4[i];
    float c0 = si.z + fcb[0];
    float c1 = si.w + fcb[1];
    auto bit = [&](int j, float ux, float uy) -> unsigned char {
        ux = fminf(fmaxf(ux, 1e-9f), 1.0f - 1e-9f);
        uy = fminf(fmaxf(uy, 1e-9f), 1.0f - 1e-9f);
        float g0 = -logf(-logf(ux));
        float g1 = -logf(-logf(uy));
        float4 sj = l4[j];
        return ((c0 + sj.x + g0) >= (c1 + sj.y + g1)) ? 1 : 0;
    };
    uchar4 r;
    r.x = bit(j0 + 0, u01.x, u01.y);
    r.y = bit(j0 + 1, u01.z, u01.w);
    r.z = bit(j0 + 2, u23.x, u23.y);
    r.w = bit(j0 + 3, u23.z, u23.w);
    *reinterpret_cast<uchar4*>(A8 + (long)(b * kN + i) * kN + j0) = r;
}

__global__ void k_colsum_part(const unsigned char* __restrict__ A8,
                              float* __restrict__ degD) {
    int b = blockIdx.x;
    int j = threadIdx.x;
    int r0 = blockIdx.y * 64;
    const unsigned char* Ab = A8 + (long)b * kN * kN;
    int s = 0;
#pragma unroll 8
    for (int r = r0; r < r0 + 64; r++) s += Ab[(long)r * kN + j];
    atomicAdd(&degD[b * kN + j], (float)s);
}

__global__ void k_rsqrtD(const float* __restrict__ degD, float* __restrict__ disD) {
    int i = blockIdx.x * 256 + threadIdx.x;
    if (i < kNTOT) disD[i] = rsqrtf(degD[i]);
}

__global__ void k_degS(const int* __restrict__ colp, int* degS) {
    int e = blockIdx.x * 256 + threadIdx.x;
    if (e < kE) atomicAdd(&degS[colp[e]], 1);
}

__global__ void k_disS(const int* __restrict__ degS, float* __restrict__ disS) {
    int n = blockIdx.x * 256 + threadIdx.x;
    if (n < kNTOT) disS[n] = rsqrtf((float)degS[n] + 1.f);
}

// exclusive prefix-sum of degS (16384) -> nodeStart, cursor; one block 1024 thr
__global__ void k_scan(const int* __restrict__ degS, int* __restrict__ ns,
                       int* __restrict__ cur) {
    __shared__ int sm[1024];
    int tid = threadIdx.x;
    int base = tid * 16;
    int local[16];
    int sum = 0;
#pragma unroll
    for (int v = 0; v < 16; v++) { local[v] = degS[base + v]; sum += local[v]; }
    sm[tid] = sum;
    __syncthreads();
    for (int off = 1; off < 1024; off <<= 1) {
        int v = (tid >= off) ? sm[tid - off] : 0;
        __syncthreads();
        sm[tid] += v;
        __syncthreads();
    }
    int run = sm[tid] - sum;   // exclusive
#pragma unroll
    for (int v = 0; v < 16; v++) {
        ns[base + v] = run;
        cur[base + v] = run;
        run += local[v];
    }
    if (tid == 1023) ns[kNTOT] = run;
}

__global__ void k_fill(const int* __restrict__ rowp, const int* __restrict__ colp,
                       int* cur, int* __restrict__ esrc) {
    int e = blockIdx.x * 256 + threadIdx.x;
    if (e < kE) {
        int c = colp[e];
        int p = atomicAdd(&cur[c], 1);
        esrc[p] = rowp[e];
    }
}

// ---------------------------------------------------------------------------
// CSR gather:  out[c] = xw[c]*dis[c]^2 + bias + sum_{e: col=c} xw[r]*dis[r]*dis[c]
// One warp per destination node. NV float4 per lane (F = NV*128).
// ---------------------------------------------------------------------------
template <int NV>
__global__ __launch_bounds__(256) void k_gather(
        const int* __restrict__ ns, const int* __restrict__ esrc,
        const float* __restrict__ xw, const float* __restrict__ disS,
        const float* __restrict__ bias, float* __restrict__ out,
        int outStride, int outOffset) {
    constexpr int F = NV * 128;
    int node = (blockIdx.x * 256 + threadIdx.x) >> 5;
    int lane = threadIdx.x & 31;
    if (node >= kNTOT) return;
    float dc = disS[node];
    float4 acc[NV];
#pragma unroll
    for (int v = 0; v < NV; v++) {
        float4 xv = *reinterpret_cast<const float4*>(xw + (long)node * F + v * 128 + lane * 4);
        float4 bb = *reinterpret_cast<const float4*>(bias + v * 128 + lane * 4);
        float d2 = dc * dc;
        acc[v] = make_float4(xv.x * d2 + bb.x, xv.y * d2 + bb.y,
                             xv.z * d2 + bb.z, xv.w * d2 + bb.w);
    }
    int s = ns[node], e = ns[node + 1];
    int i = s;
    for (; i + 4 <= e; i += 4) {
        int r0 = esrc[i], r1 = esrc[i + 1], r2 = esrc[i + 2], r3 = esrc[i + 3];
        float s0 = disS[r0] * dc, s1 = disS[r1] * dc;
        float s2 = disS[r2] * dc, s3 = disS[r3] * dc;
#pragma unroll
        for (int v = 0; v < NV; v++) {
            int off = v * 128 + lane * 4;
            float4 x0 = *reinterpret_cast<const float4*>(xw + (long)r0 * F + off);
            float4 x1 = *reinterpret_cast<const float4*>(xw + (long)r1 * F + off);
            float4 x2 = *reinterpret_cast<const float4*>(xw + (long)r2 * F + off);
            float4 x3 = *reinterpret_cast<const float4*>(xw + (long)r3 * F + off);
            acc[v].x += x0.x * s0 + x1.x * s1 + x2.x * s2 + x3.x * s3;
            acc[v].y += x0.y * s0 + x1.y * s1 + x2.y * s2 + x3.y * s3;
            acc[v].z += x0.z * s0 + x1.z * s1 + x2.z * s2 + x3.z * s3;
            acc[v].w += x0.w * s0 + x1.w * s1 + x2.w * s2 + x3.w * s3;
        }
    }
    for (; i < e; i++) {
        int r = esrc[i];
        float sr = disS[r] * dc;
#pragma unroll
        for (int v = 0; v < NV; v++) {
            int off = v * 128 + lane * 4;
            float4 xv = *reinterpret_cast<const float4*>(xw + (long)r * F + off);
            acc[v].x += xv.x * sr; acc[v].y += xv.y * sr;
            acc[v].z += xv.z * sr; acc[v].w += xv.w * sr;
        }
    }
#pragma unroll
    for (int v = 0; v < NV; v++)
        *reinterpret_cast<float4*>(out + (long)node * outStride + outOffset +
                                   v * 128 + lane * 4) = acc[v];
}

// ---------------------------------------------------------------------------
// tf32 NT GEMM (unchanged from R3): C[MxNf] = A[MxK] @ B[NfxK]^T
// ---------------------------------------------------------------------------
template <bool RELU_A>
__global__ __launch_bounds__(256) void k_gemm_tf32(
        const float* __restrict__ A, long aStride,
        const float* __restrict__ B,
        float* __restrict__ C, long cStride,
        int Nf, int K) {
    __shared__ uint32_t As[2][128][20];
    __shared__ uint32_t Bs[2][128][20];
    const float* Ab = A + (long)blockIdx.z * aStride;
    float* Cb = C + (long)blockIdx.z * cStride;
    int m0 = blockIdx.y * 128, n0 = blockIdx.x * 128;
    int t = threadIdx.x;
    int wid = t >> 5, lane = t & 31;
    int mw = (wid >> 1) * 32, nw = (wid & 1) * 64;
    int g = lane >> 2, tg = lane & 3;
    int lr = t >> 2, lc = (t & 3) << 2;

    float acc[2][8][4];
#pragma unroll
    for (int i = 0; i < 2; i++)
#pragma unroll
        for (int j = 0; j < 8; j++)
#pragma unroll
            for (int c = 0; c < 4; c++) acc[i][j][c] = 0.f;

    const float* aP0 = Ab + (long)(m0 + lr) * K + lc;
    const float* aP1 = Ab + (long)(m0 + lr + 64) * K + lc;
    const float* bP0 = B + (long)(n0 + lr) * K + lc;
    const float* bP1 = B + (long)(n0 + lr + 64) * K + lc;

    auto cvt4 = [](float4 v, bool relu) -> uint4 {
        if (relu) {
            v.x = fmaxf(v.x, 0.f); v.y = fmaxf(v.y, 0.f);
            v.z = fmaxf(v.z, 0.f); v.w = fmaxf(v.w, 0.f);
        }
        uint4 r;
        r.x = f2tf(v.x); r.y = f2tf(v.y); r.z = f2tf(v.z); r.w = f2tf(v.w);
        return r;
    };

    {
        uint4 a0 = cvt4(*reinterpret_cast<const float4*>(aP0), RELU_A);
        uint4 a1 = cvt4(*reinterpret_cast<const float4*>(aP1), RELU_A);
        uint4 b0 = cvt4(*reinterpret_cast<const float4*>(bP0), false);
        uint4 b1 = cvt4(*reinterpret_cast<const float4*>(bP1), false);
        *reinterpret_cast<uint4*>(&As[0][lr][lc]) = a0;
        *reinterpret_cast<uint4*>(&As[0][lr + 64][lc]) = a1;
        *reinterpret_cast<uint4*>(&Bs[0][lr][lc]) = b0;
        *reinterpret_cast<uint4*>(&Bs[0][lr + 64][lc]) = b1;
    }
    __syncthreads();

    int buf = 0;
    for (int k0 = 0; k0 < K; k0 += 16) {
        bool more = (k0 + 16) < K;
        float4 na0, na1, nb0, nb1;
        if (more) {
            na0 = *reinterpret_cast<const float4*>(aP0 + k0 + 16);
            na1 = *reinterpret_cast<const float4*>(aP1 + k0 + 16);
            nb0 = *reinterpret_cast<const float4*>(bP0 + k0 + 16);
            nb1 = *reinterpret_cast<const float4*>(bP1 + k0 + 16);
        }
#pragma unroll
        for (int s = 0; s < 2; s++) {
            int kk = s * 8 + tg;
            uint32_t af[2][4];
#pragma unroll
            for (int mt = 0; mt < 2; mt++) {
                int r = mw + mt * 16 + g;
                af[mt][0] = As[buf][r][kk];
                af[mt][1] = As[buf][r + 8][kk];
                af[mt][2] = As[buf][r][kk + 4];
                af[mt][3] = As[buf][r + 8][kk + 4];
            }
#pragma unroll
            for (int j = 0; j < 8; j++) {
                int nr = nw + j * 8 + g;
                uint32_t b0 = Bs[buf][nr][kk];
                uint32_t b1 = Bs[buf][nr][kk + 4];
                mma_tf32(acc[0][j], af[0], b0, b1);
                mma_tf32(acc[1][j], af[1], b0, b1);
            }
        }
        if (more) {
            int nb = buf ^ 1;
            *reinterpret_cast<uint4*>(&As[nb][lr][lc]) = cvt4(na0, RELU_A);
            *reinterpret_cast<uint4*>(&As[nb][lr + 64][lc]) = cvt4(na1, RELU_A);
            *reinterpret_cast<uint4*>(&Bs[nb][lr][lc]) = cvt4(nb0, false);
            *reinterpret_cast<uint4*>(&Bs[nb][lr + 64][lc]) = cvt4(nb1, false);
            __syncthreads();
            buf = nb;
        }
    }

#pragma unroll
    for (int mt = 0; mt < 2; mt++) {
        int row = m0 + mw + mt * 16 + g;
#pragma unroll
        for (int j = 0; j < 8; j++) {
            int col = n0 + nw + j * 8 + 2 * tg;
            *reinterpret_cast<float2*>(Cb + (long)row * Nf + col) =
                make_float2(acc[mt][j][0], acc[mt][j][1]);
            *reinterpret_cast<float2*>(Cb + (long)(row + 8) * Nf + col) =
                make_float2(acc[mt][j][2], acc[mt][j][3]);
        }
    }
}

// ---------------------------------------------------------------------------
// tf32 dense GCN propagation — A tiles loaded as uint8 and expanded to tf32.
// ---------------------------------------------------------------------------
template <bool RELU>
__global__ __launch_bounds__(256) void k_prop_tf32(
        const unsigned char* __restrict__ Adj8, const float* __restrict__ XW,
        const float* __restrict__ dis, const float* __restrict__ bias,
        float* __restrict__ out, int F, int outStride, int outOffset) {
    __shared__ uint32_t As[2][16][136];
    __shared__ uint32_t Bs[2][16][136];
    int b = blockIdx.z;
    const unsigned char* Ab = Adj8 + (long)b * kN * kN;
    const float* Xb = XW + (long)b * kN * F;
    const float* db = dis + b * kN;
    float* Ob = out + (long)b * kN * outStride + outOffset;
    int i0 = blockIdx.y * 128, f0 = blockIdx.x * 128;
    int t = threadIdx.x;
    int wid = t >> 5, lane = t & 31;
    int mw = (wid >> 1) * 32, nw = (wid & 1) * 64;
    int g = lane >> 2, tg = lane & 3;
    int jj = t >> 4;
    int ii = (t & 15) << 3;

    float acc[2][8][4];
#pragma unroll
    for (int i = 0; i < 2; i++)
#pragma unroll
        for (int j = 0; j < 8; j++)
#pragma unroll
            for (int c = 0; c < 4; c++) acc[i][j][c] = 0.f;

    constexpr uint32_t ONE = 0x3F800000u;
    auto stTile = [&](int bufI, uint2 rawA, float4 x0, float4 x1, float dj) {
        uint4 ua0, ua1, ux0, ux1;
        ua0.x = (rawA.x & 0xffu)         ? ONE : 0u;
        ua0.y = ((rawA.x >> 8) & 0xffu)  ? ONE : 0u;
        ua0.z = ((rawA.x >> 16) & 0xffu) ? ONE : 0u;
        ua0.w = ((rawA.x >> 24) & 0xffu) ? ONE : 0u;
        ua1.x = (rawA.y & 0xffu)         ? ONE : 0u;
        ua1.y = ((rawA.y >> 8) & 0xffu)  ? ONE : 0u;
        ua1.z = ((rawA.y >> 16) & 0xffu) ? ONE : 0u;
        ua1.w = ((rawA.y >> 24) & 0xffu) ? ONE : 0u;
        ux0.x = f2tf(x0.x * dj); ux0.y = f2tf(x0.y * dj);
        ux0.z = f2tf(x0.z * dj); ux0.w = f2tf(x0.w * dj);
        ux1.x = f2tf(x1.x * dj); ux1.y = f2tf(x1.y * dj);
        ux1.z = f2tf(x1.z * dj); ux1.w = f2tf(x1.w * dj);
        *reinterpret_cast<uint4*>(&As[bufI][jj][ii]) = ua0;
        *reinterpret_cast<uint4*>(&As[bufI][jj][ii + 4]) = ua1;
        *reinterpret_cast<uint4*>(&Bs[bufI][jj][ii]) = ux0;
        *reinterpret_cast<uint4*>(&Bs[bufI][jj][ii + 4]) = ux1;
    };

    {
        uint2 rawA = *reinterpret_cast<const uint2*>(Ab + (long)jj * kN + i0 + ii);
        const float* xp = Xb + (long)jj * F + f0 + ii;
        stTile(0, rawA,
               *reinterpret_cast<const float4*>(xp),
               *reinterpret_cast<const float4*>(xp + 4),
               db[jj]);
    }
    __syncthreads();

    int buf = 0;
    for (int j0 = 0; j0 < kN; j0 += 16) {
        bool more = (j0 + 16) < kN;
        uint2 nraw;
        float4 nx0, nx1;
        float djn = 0.f;
        if (more) {
            nraw = *reinterpret_cast<const uint2*>(
                Ab + (long)(j0 + 16 + jj) * kN + i0 + ii);
            const float* xp = Xb + (long)(j0 + 16 + jj) * F + f0 + ii;
            nx0 = *reinterpret_cast<const float4*>(xp);
            nx1 = *reinterpret_cast<const float4*>(xp + 4);
            djn = db[j0 + 16 + jj];
        }
#pragma unroll
        for (int s = 0; s < 2; s++) {
            int kk = s * 8 + tg;
            uint32_t af[2][4];
#pragma unroll
            for (int mt = 0; mt < 2; mt++) {
                int m = mw + mt * 16 + g;
                af[mt][0] = As[buf][kk][m];
                af[mt][1] = As[buf][kk][m + 8];
                af[mt][2] = As[buf][kk + 4][m];
                af[mt][3] = As[buf][kk + 4][m + 8];
            }
#pragma unroll
            for (int j = 0; j < 8; j++) {
                int n = nw + j * 8 + g;
                uint32_t b0 = Bs[buf][kk][n];
                uint32_t b1 = Bs[buf][kk + 4][n];
                mma_tf32(acc[0][j], af[0], b0, b1);
                mma_tf32(acc[1][j], af[1], b0, b1);
            }
        }
        if (more) {
            int nb = buf ^ 1;
            stTile(nb, nraw, nx0, nx1, djn);
            __syncthreads();
            buf = nb;
        }
    }

#pragma unroll
    for (int mt = 0; mt < 2; mt++) {
        int rowA = i0 + mw + mt * 16 + g;
        float diA = db[rowA], diB = db[rowA + 8];
#pragma unroll
        for (int j = 0; j < 8; j++) {
            int col = f0 + nw + j * 8 + 2 * tg;
            float2 bb = *reinterpret_cast<const float2*>(bias + col);
            float2 xA = *reinterpret_cast<const float2*>(Xb + (long)rowA * F + col);
            float2 xB = *reinterpret_cast<const float2*>(Xb + (long)(rowA + 8) * F + col);
            float v0 = diA * (acc[mt][j][0] + diA * xA.x) + bb.x;
            float v1 = diA * (acc[mt][j][1] + diA * xA.y) + bb.y;
            float v2 = diB * (acc[mt][j][2] + diB * xB.x) + bb.x;
            float v3 = diB * (acc[mt][j][3] + diB * xB.y) + bb.y;
            if (RELU) {
                v0 = fmaxf(v0, 0.f); v1 = fmaxf(v1, 0.f);
                v2 = fmaxf(v2, 0.f); v3 = fmaxf(v3, 0.f);
            }
            *reinterpret_cast<float2*>(Ob + (long)rowA * outStride + col) =
                make_float2(v0, v1);
            *reinterpret_cast<float2*>(Ob + (long)(rowA + 8) * outStride + col) =
                make_float2(v2, v3);
        }
    }
}

// ---------------------------------------------------------------------------
// fcn1 split-K + head (unchanged)
// ---------------------------------------------------------------------------
__global__ void k_fcn1(const float* __restrict__ emb, const float* __restrict__ W,
                       float* __restrict__ h1) {
    constexpr int KC = kKTOT / 128;
    __shared__ float As[16][32];
    __shared__ float Bs[16][64];
    int n0 = blockIdx.x * 64;
    int kbase = blockIdx.y * KC;
    int t = threadIdx.x;
    int m = t & 31;
    int nb = (t >> 5) << 3;
    float acc[8];
#pragma unroll
    for (int j = 0; j < 8; j++) acc[j] = 0.f;

    for (int k0 = kbase; k0 < kbase + KC; k0 += 16) {
        if (t < 128) {
            int row = t >> 2, c4 = (t & 3) << 2;
            float4 a = *reinterpret_cast<const float4*>(emb + (long)row * kKTOT + k0 + c4);
            As[c4 + 0][row] = a.x; As[c4 + 1][row] = a.y;
            As[c4 + 2][row] = a.z; As[c4 + 3][row] = a.w;
        }
        {
            int row = t >> 2, c4 = (t & 3) << 2;
            float4 b = *reinterpret_cast<const float4*>(W + (long)(n0 + row) * kKTOT + k0 + c4);
            Bs[c4 + 0][row] = b.x; Bs[c4 + 1][row] = b.y;
            Bs[c4 + 2][row] = b.z; Bs[c4 + 3][row] = b.w;
        }
        __syncthreads();
#pragma unroll
        for (int k = 0; k < 16; k++) {
            float a = As[k][m];
#pragma unroll
            for (int j = 0; j < 8; j++) acc[j] += a * Bs[k][nb + j];
        }
        __syncthreads();
    }
#pragma unroll
    for (int j = 0; j < 8; j++)
        atomicAdd(&h1[m * 256 + n0 + nb + j], acc[j]);
}

__global__ void k_fcn23(const float* __restrict__ h1g,
                        const float* __restrict__ b1, const float* __restrict__ w2,
                        const float* __restrict__ b2, const float* __restrict__ w3,
                        const float* __restrict__ b3, float* __restrict__ out) {
    __shared__ float h1s[32][256];
    __shared__ float h2s[32][32];
    int t = threadIdx.x;
    for (int idx = t; idx < 32 * 256; idx += 1024) {
        float v = h1g[idx] + b1[idx & 255];
        h1s[idx >> 8][idx & 255] = (v >= 0.f) ? v : 0.2f * v;
    }
    __syncthreads();
    {
        int b = t >> 5, o = t & 31;
        float s = 0.f;
#pragma unroll 8
        for (int k = 0; k < 256; k++) s += h1s[b][k] * w2[o * 256 + k];
        s += b2[o];
        h2s[b][o] = (s >= 0.f) ? s : 0.2f * s;
    }
    __syncthreads();
    if (t < 64) {
        int b = t >> 1, o = t & 1;
        float s = 0.f;
#pragma unroll
        for (int k = 0; k < 32; k++) s += h2s[b][k] * w3[o * 32 + k];
        out[b * 2 + o] = s + b3[o];
    }
}

// ---------------------------------------------------------------------------
// Launch
// ---------------------------------------------------------------------------
extern "C" void kernel_launch(void* const* d_in, const int* in_sizes, int n_in,
                              void* d_out, int out_size) {
    const float* x    = (const float*)d_in[0];
    const float* t    = (const float*)d_in[1];
    const float* gu   = (const float*)d_in[2];
    const int*   ei   = (const int*)d_in[3];
    const float* w1   = (const float*)d_in[4];
    const float* b1   = (const float*)d_in[5];
    const float* w2   = (const float*)d_in[6];
    const float* b2   = (const float*)d_in[7];
    const float* fcw  = (const float*)d_in[8];
    const float* fcb  = (const float*)d_in[9];
    const float* f1w  = (const float*)d_in[10];
    const float* f1b  = (const float*)d_in[11];
    const float* f2w  = (const float*)d_in[12];
    const float* f2b  = (const float*)d_in[13];
    const float* f3w  = (const float*)d_in[14];
    const float* f3b  = (const float*)d_in[15];
    float* out = (float*)d_out;

    const int* rowp = ei;
    const int* colp = ei + kE;

    float* base = nullptr;
    cudaGetSymbolAddress((void**)&base, g_scratch);
    float* p_lslr = base + OFF_LSLR;
    unsigned char* p_A8 = (unsigned char*)(base + OFF_A8);
    float* p_disD = base + OFF_DISD;
    float* p_xw1  = base + OFF_XW1;
    float* p_h    = base + OFF_H;
    float* p_xw2  = base + OFF_XW2;
    float* p_emb  = base + OFF_EMB;
    float* p_disS = base + OFF_DISS;
    int*   p_degS = (int*)(base + OFF_DEGS);
    float* p_xws1 = base + OFF_XWS1;
    float* p_sc1  = base + OFF_SC1;
    float* p_xws2 = base + OFF_XWS2;
    float* p_h1   = base + OFF_H1;
    float* p_degD = base + OFF_DEGD;
    int*   p_ns   = (int*)(base + OFF_NS);
    int*   p_cur  = (int*)(base + OFF_CUR);
    int*   p_esrc = (int*)(base + OFF_ESRC);

    k_zero<<<64, 256>>>(p_degS, p_h1, p_degD);

    // Gumbel adjacency (u8)
    k_lslr<<<kNTOT / 8, 256>>>(t, fcw, p_lslr);
    k_buildA<<<kBZ * kN * kN / 1024, 256>>>(gu, fcb, p_lslr, p_A8);
    k_colsum_part<<<dim3(kBZ, 8), kN>>>(p_A8, p_degD);
    k_rsqrtD<<<kNTOT / 256, 256>>>(p_degD, p_disD);

    // sparse degrees + CSR
    k_degS<<<kE / 256, 256>>>(colp, p_degS);
    k_disS<<<kNTOT / 256, 256>>>(p_degS, p_disS);
    k_scan<<<1, 1024>>>(p_degS, p_ns, p_cur);
    k_fill<<<kE / 256, 256>>>(rowp, colp, p_cur, p_esrc);

    // dense GCN layer 1
    k_gemm_tf32<false><<<dim3(kF1 / 128, kN / 128, kBZ), 256>>>(
        x, (long)kN * kN, w1, p_xw1, (long)kN * kF1, kF1, kN);
    k_prop_tf32<true><<<dim3(kF1 / 128, kN / 128, kBZ), 256>>>(
        p_A8, p_xw1, p_disD, b1, p_h, kF1, kF1, 0);

    // dense GCN layer 2 -> emb[:, 0:128]
    k_gemm_tf32<false><<<dim3(kF2 / 128, kN / 128, kBZ), 256>>>(
        p_h, (long)kN * kF1, w2, p_xw2, (long)kN * kF2, kF2, kF1);
    k_prop_tf32<false><<<dim3(kF2 / 128, kN / 128, kBZ), 256>>>(
        p_A8, p_xw2, p_disD, b2, p_emb, kF2, 256, 0);

    // sparse GCN layer 1 (CSR gather)
    k_gemm_tf32<false><<<dim3(kF1 / 128, kNTOT / 128, 1), 256>>>(
        x, 0, w1, p_xws1, 0, kF1, kN);
    k_gather<2><<<kNTOT / 8, 256>>>(p_ns, p_esrc, p_xws1, p_disS, b1,
                                    p_sc1, kF1, 0);

    // sparse GCN layer 2 -> emb[:, 128:256]
    k_gemm_tf32<true><<<dim3(kF2 / 128, kNTOT / 128, 1), 256>>>(
        p_sc1, 0, w2, p_xws2, 0, kF2, kF1);
    k_gather<1><<<kNTOT / 8, 256>>>(p_ns, p_esrc, p_xws2, p_disS, b2,
                                    p_emb, 256, 128);

    // MLP head
    k_fcn1<<<dim3(256 / 64, 128), 256>>>(p_emb, f1w, p_h1);
    k_fcn23<<<1, 1024>>>(p_h1, f1b, f2w, f2b, f3w, f3b, out);
}

// round 5
// speedup vs baseline: 2.0136x; 1.1196x over previous
#include <cuda_runtime.h>
#include <cstdint>

// ---------------------------------------------------------------------------
// Problem constants
// ---------------------------------------------------------------------------
constexpr int kN    = 512;
constexpr int kBZ   = 32;
constexpr int kTC   = 256;
constexpr int kF1   = 256;
constexpr int kF2   = 128;
constexpr int kE    = 524288;
constexpr int kNTOT = kBZ * kN;          // 16384
constexpr int kKTOT = kF2 * 2 * kN;      // 131072

// ---------------------------------------------------------------------------
// Scratch (offsets in floats)
// ---------------------------------------------------------------------------
constexpr long OFF_EG   = 0;                                     // E[kNTOT]
constexpr long OFF_FG   = OFF_EG   + (long)kNTOT;                // F[kNTOT]
constexpr long OFF_A8   = OFF_FG   + (long)kNTOT;                // u8 view
constexpr long OFF_DISD = OFF_A8   + (long)kBZ * kN * kN / 4;
constexpr long OFF_XW1  = OFF_DISD + (long)kNTOT;
constexpr long OFF_H    = OFF_XW1  + (long)kNTOT * kF1;
constexpr long OFF_XW2  = OFF_H    + (long)kNTOT * kF1;
constexpr long OFF_EMB  = OFF_XW2  + (long)kNTOT * kF2;
constexpr long OFF_DISS = OFF_EMB  + (long)kNTOT * 256;
constexpr long OFF_DEGS = OFF_DISS + (long)kNTOT;                // int
constexpr long OFF_SC1  = OFF_DEGS + (long)kNTOT;
constexpr long OFF_XWS2 = OFF_SC1  + (long)kNTOT * kF1;
constexpr long OFF_H1   = OFF_XWS2 + (long)kNTOT * kF2;
constexpr long OFF_DEGD = OFF_H1   + (long)kBZ * 256;
constexpr long OFF_NS   = OFF_DEGD + (long)kNTOT;                // int, kNTOT+1
constexpr long OFF_CUR  = OFF_NS   + (long)kNTOT + 4;            // int
constexpr long OFF_ESRC = OFF_CUR  + (long)kNTOT;                // int, kE
constexpr long SCRATCH_FLOATS = OFF_ESRC + (long)kE;

__device__ __align__(16) float g_scratch[SCRATCH_FLOATS];

// ---------------------------------------------------------------------------
// tf32 helpers
// ---------------------------------------------------------------------------
__device__ __forceinline__ uint32_t f2tf(float x) {
    uint32_t r;
    asm("cvt.rna.tf32.f32 %0, %1;" : "=r"(r) : "f"(x));
    return r;
}
__device__ __forceinline__ void mma_tf32(float* d, const uint32_t* a,
                                         uint32_t b0, uint32_t b1) {
    asm volatile(
        "mma.sync.aligned.m16n8k8.row.col.f32.tf32.tf32.f32 "
        "{%0,%1,%2,%3},{%4,%5,%6,%7},{%8,%9},{%0,%1,%2,%3};"
        : "+f"(d[0]), "+f"(d[1]), "+f"(d[2]), "+f"(d[3])
        : "r"(a[0]), "r"(a[1]), "r"(a[2]), "r"(a[3]), "r"(b0), "r"(b1));
}

// ---------------------------------------------------------------------------
// Small kernels
// ---------------------------------------------------------------------------
__global__ void k_zero(int* degS, float* h1, float* degD) {
    int i = blockIdx.x * 256 + threadIdx.x;
    if (i < kNTOT) { degS[i] = 0; degD[i] = 1.f; }
    if (i < kBZ * 256) h1[i] = 0.f;
}

// per node: u=relu(t); ls=u@Ws.T, lr=u@Wr.T; E=exp(lr1-lr0+b1-b0), F=exp(ls1-ls0)
__global__ void k_lslr(const float* __restrict__ t, const float* __restrict__ fcw,
                       const float* __restrict__ fcb,
                       float* __restrict__ Eg, float* __restrict__ Fg) {
    int warp = (blockIdx.x * blockDim.x + threadIdx.x) >> 5;
    int lane = threadIdx.x & 31;
    if (warp >= kNTOT) return;
    const float* tn = t + (long)warp * kTC;
    const float* w0 = fcw;
    const float* w1 = fcw + 512;
    float s0 = 0.f, s1 = 0.f, r0 = 0.f, r1 = 0.f;
#pragma unroll
    for (int q = 0; q < 8; q++) {
        int d = lane + 32 * q;
        float u = fmaxf(tn[d], 0.f);
        s0 += u * w0[d];       s1 += u * w1[d];
        r0 += u * w0[256 + d]; r1 += u * w1[256 + d];
    }
#pragma unroll
    for (int off = 16; off; off >>= 1) {
        s0 += __shfl_down_sync(0xffffffffu, s0, off);
        s1 += __shfl_down_sync(0xffffffffu, s1, off);
        r0 += __shfl_down_sync(0xffffffffu, r0, off);
        r1 += __shfl_down_sync(0xffffffffu, r1, off);
    }
    if (lane == 0) {
        Eg[warp] = expf(r1 - r0 + fcb[1] - fcb[0]);
        Fg[warp] = expf(s1 - s0);
    }
}

// A8[b][i][j] = (y0>=y1) via l1 >= l0*E_i*F_j, l=-log(clamp(u))
__global__ void k_buildA(const float* __restrict__ gu,
                         const float* __restrict__ Eg, const float* __restrict__ Fg,
                         unsigned char* __restrict__ A8) {
    int idx = blockIdx.x * 256 + threadIdx.x;      // 2,097,152
    int j0 = (idx & 127) << 2;
    int i  = (idx >> 7) & 511;
    int b  = idx >> 16;
    float Ei = Eg[b * kN + i];
    float4 Fv = *reinterpret_cast<const float4*>(Fg + b * kN + j0);
    const float4* g4 = reinterpret_cast<const float4*>(
        gu + ((long)(b * kN + i) * kN + j0) * 2);
    float4 u01 = g4[0];
    float4 u23 = g4[1];
    auto bit = [&](float ux, float uy, float Fj) -> unsigned char {
        ux = fminf(fmaxf(ux, 1e-9f), 1.0f - 1e-9f);
        uy = fminf(fmaxf(uy, 1e-9f), 1.0f - 1e-9f);
        float l0 = -logf(ux);
        float l1 = -logf(uy);
        return (l1 >= l0 * Ei * Fj) ? 1 : 0;
    };
    uchar4 r;
    r.x = bit(u01.x, u01.y, Fv.x);
    r.y = bit(u01.z, u01.w, Fv.y);
    r.z = bit(u23.x, u23.y, Fv.z);
    r.w = bit(u23.z, u23.w, Fv.w);
    *reinterpret_cast<uchar4*>(A8 + (long)(b * kN + i) * kN + j0) = r;
}

__global__ void k_colsum_part(const unsigned char* __restrict__ A8,
                              float* __restrict__ degD) {
    int b = blockIdx.x;
    int j = threadIdx.x;
    int r0 = blockIdx.y * 64;
    const unsigned char* Ab = A8 + (long)b * kN * kN;
    int s = 0;
#pragma unroll 8
    for (int r = r0; r < r0 + 64; r++) s += Ab[(long)r * kN + j];
    atomicAdd(&degD[b * kN + j], (float)s);
}

__global__ void k_degS(const int* __restrict__ colp, int* degS) {
    int e = blockIdx.x * 256 + threadIdx.x;
    if (e < kE) atomicAdd(&degS[colp[e]], 1);
}

// disD = rsqrt(degD); disS = rsqrt(degS+1)
__global__ void k_dis(const float* __restrict__ degD, const int* __restrict__ degS,
                      float* __restrict__ disD, float* __restrict__ disS) {
    int i = blockIdx.x * 256 + threadIdx.x;
    if (i < kNTOT) {
        disD[i] = rsqrtf(degD[i]);
        disS[i] = rsqrtf((float)degS[i] + 1.f);
    }
}

// exclusive prefix-sum of degS (16384) -> nodeStart, cursor
__global__ void k_scan(const int* __restrict__ degS, int* __restrict__ ns,
                       int* __restrict__ cur) {
    __shared__ int sm[1024];
    int tid = threadIdx.x;
    int base = tid * 16;
    int local[16];
    int sum = 0;
#pragma unroll
    for (int v = 0; v < 16; v++) { local[v] = degS[base + v]; sum += local[v]; }
    sm[tid] = sum;
    __syncthreads();
    for (int off = 1; off < 1024; off <<= 1) {
        int v = (tid >= off) ? sm[tid - off] : 0;
        __syncthreads();
        sm[tid] += v;
        __syncthreads();
    }
    int run = sm[tid] - sum;
#pragma unroll
    for (int v = 0; v < 16; v++) {
        ns[base + v] = run;
        cur[base + v] = run;
        run += local[v];
    }
    if (tid == 1023) ns[kNTOT] = run;
}

__global__ void k_fill(const int* __restrict__ rowp, const int* __restrict__ colp,
                       int* cur, int* __restrict__ esrc) {
    int e = blockIdx.x * 256 + threadIdx.x;
    if (e < kE) {
        int c = colp[e];
        int p = atomicAdd(&cur[c], 1);
        esrc[p] = rowp[e];
    }
}

// ---------------------------------------------------------------------------
// CSR gather: WPN warps per node, each covers 128 features (F = WPN*128).
// out[c] = xw[c]*dis[c]^2 + bias + sum_e xw[r]*dis[r]*dis[c]
// ---------------------------------------------------------------------------
template <int WPN>
__global__ __launch_bounds__(256) void k_gather(
        const int* __restrict__ ns, const int* __restrict__ esrc,
        const float* __restrict__ xw, const float* __restrict__ disS,
        const float* __restrict__ bias, float* __restrict__ out,
        int outStride, int outOffset) {
    constexpr int F = WPN * 128;
    int gw = (blockIdx.x * 256 + threadIdx.x) >> 5;
    int lane = threadIdx.x & 31;
    int node = gw / WPN;
    int part = gw % WPN;
    if (node >= kNTOT) return;
    int off = part * 128 + lane * 4;
    float dc = disS[node];
    float4 acc;
    {
        float4 xv = *reinterpret_cast<const float4*>(xw + (long)node * F + off);
        float4 bb = *reinterpret_cast<const float4*>(bias + off);
        float d2 = dc * dc;
        acc = make_float4(xv.x * d2 + bb.x, xv.y * d2 + bb.y,
                          xv.z * d2 + bb.z, xv.w * d2 + bb.w);
    }
    int s = ns[node], e = ns[node + 1];
    int i = s;
    for (; i + 4 <= e; i += 4) {
        int r0 = esrc[i], r1 = esrc[i + 1], r2 = esrc[i + 2], r3 = esrc[i + 3];
        float s0 = disS[r0] * dc, s1 = disS[r1] * dc;
        float s2 = disS[r2] * dc, s3 = disS[r3] * dc;
        float4 x0 = *reinterpret_cast<const float4*>(xw + (long)r0 * F + off);
        float4 x1 = *reinterpret_cast<const float4*>(xw + (long)r1 * F + off);
        float4 x2 = *reinterpret_cast<const float4*>(xw + (long)r2 * F + off);
        float4 x3 = *reinterpret_cast<const float4*>(xw + (long)r3 * F + off);
        acc.x += x0.x * s0 + x1.x * s1 + x2.x * s2 + x3.x * s3;
        acc.y += x0.y * s0 + x1.y * s1 + x2.y * s2 + x3.y * s3;
        acc.z += x0.z * s0 + x1.z * s1 + x2.z * s2 + x3.z * s3;
        acc.w += x0.w * s0 + x1.w * s1 + x2.w * s2 + x3.w * s3;
    }
    for (; i < e; i++) {
        int r = esrc[i];
        float sr = disS[r] * dc;
        float4 xv = *reinterpret_cast<const float4*>(xw + (long)r * F + off);
        acc.x += xv.x * sr; acc.y += xv.y * sr;
        acc.z += xv.z * sr; acc.w += xv.w * sr;
    }
    *reinterpret_cast<float4*>(out + (long)node * outStride + outOffset + off) = acc;
}

// ---------------------------------------------------------------------------
// tf32 NT GEMM: C[MxNf] = A[MxK] @ B[NfxK]^T
// ---------------------------------------------------------------------------
template <bool RELU_A>
__global__ __launch_bounds__(256) void k_gemm_tf32(
        const float* __restrict__ A, long aStride,
        const float* __restrict__ B,
        float* __restrict__ C, long cStride,
        int Nf, int K) {
    __shared__ uint32_t As[2][128][20];
    __shared__ uint32_t Bs[2][128][20];
    const float* Ab = A + (long)blockIdx.z * aStride;
    float* Cb = C + (long)blockIdx.z * cStride;
    int m0 = blockIdx.y * 128, n0 = blockIdx.x * 128;
    int t = threadIdx.x;
    int wid = t >> 5, lane = t & 31;
    int mw = (wid >> 1) * 32, nw = (wid & 1) * 64;
    int g = lane >> 2, tg = lane & 3;
    int lr = t >> 2, lc = (t & 3) << 2;

    float acc[2][8][4];
#pragma unroll
    for (int i = 0; i < 2; i++)
#pragma unroll
        for (int j = 0; j < 8; j++)
#pragma unroll
            for (int c = 0; c < 4; c++) acc[i][j][c] = 0.f;

    const float* aP0 = Ab + (long)(m0 + lr) * K + lc;
    const float* aP1 = Ab + (long)(m0 + lr + 64) * K + lc;
    const float* bP0 = B + (long)(n0 + lr) * K + lc;
    const float* bP1 = B + (long)(n0 + lr + 64) * K + lc;

    auto cvt4 = [](float4 v, bool relu) -> uint4 {
        if (relu) {
            v.x = fmaxf(v.x, 0.f); v.y = fmaxf(v.y, 0.f);
            v.z = fmaxf(v.z, 0.f); v.w = fmaxf(v.w, 0.f);
        }
        uint4 r;
        r.x = f2tf(v.x); r.y = f2tf(v.y); r.z = f2tf(v.z); r.w = f2tf(v.w);
        return r;
    };

    {
        uint4 a0 = cvt4(*reinterpret_cast<const float4*>(aP0), RELU_A);
        uint4 a1 = cvt4(*reinterpret_cast<const float4*>(aP1), RELU_A);
        uint4 b0 = cvt4(*reinterpret_cast<const float4*>(bP0), false);
        uint4 b1 = cvt4(*reinterpret_cast<const float4*>(bP1), false);
        *reinterpret_cast<uint4*>(&As[0][lr][lc]) = a0;
        *reinterpret_cast<uint4*>(&As[0][lr + 64][lc]) = a1;
        *reinterpret_cast<uint4*>(&Bs[0][lr][lc]) = b0;
        *reinterpret_cast<uint4*>(&Bs[0][lr + 64][lc]) = b1;
    }
    __syncthreads();

    int buf = 0;
    for (int k0 = 0; k0 < K; k0 += 16) {
        bool more = (k0 + 16) < K;
        float4 na0, na1, nb0, nb1;
        if (more) {
            na0 = *reinterpret_cast<const float4*>(aP0 + k0 + 16);
            na1 = *reinterpret_cast<const float4*>(aP1 + k0 + 16);
            nb0 = *reinterpret_cast<const float4*>(bP0 + k0 + 16);
            nb1 = *reinterpret_cast<const float4*>(bP1 + k0 + 16);
        }
#pragma unroll
        for (int s = 0; s < 2; s++) {
            int kk = s * 8 + tg;
            uint32_t af[2][4];
#pragma unroll
            for (int mt = 0; mt < 2; mt++) {
                int r = mw + mt * 16 + g;
                af[mt][0] = As[buf][r][kk];
                af[mt][1] = As[buf][r + 8][kk];
                af[mt][2] = As[buf][r][kk + 4];
                af[mt][3] = As[buf][r + 8][kk + 4];
            }
#pragma unroll
            for (int j = 0; j < 8; j++) {
                int nr = nw + j * 8 + g;
                uint32_t b0 = Bs[buf][nr][kk];
                uint32_t b1 = Bs[buf][nr][kk + 4];
                mma_tf32(acc[0][j], af[0], b0, b1);
                mma_tf32(acc[1][j], af[1], b0, b1);
            }
        }
        if (more) {
            int nb = buf ^ 1;
            *reinterpret_cast<uint4*>(&As[nb][lr][lc]) = cvt4(na0, RELU_A);
            *reinterpret_cast<uint4*>(&As[nb][lr + 64][lc]) = cvt4(na1, RELU_A);
            *reinterpret_cast<uint4*>(&Bs[nb][lr][lc]) = cvt4(nb0, false);
            *reinterpret_cast<uint4*>(&Bs[nb][lr + 64][lc]) = cvt4(nb1, false);
            __syncthreads();
            buf = nb;
        }
    }

#pragma unroll
    for (int mt = 0; mt < 2; mt++) {
        int row = m0 + mw + mt * 16 + g;
#pragma unroll
        for (int j = 0; j < 8; j++) {
            int col = n0 + nw + j * 8 + 2 * tg;
            *reinterpret_cast<float2*>(Cb + (long)row * Nf + col) =
                make_float2(acc[mt][j][0], acc[mt][j][1]);
            *reinterpret_cast<float2*>(Cb + (long)(row + 8) * Nf + col) =
                make_float2(acc[mt][j][2], acc[mt][j][3]);
        }
    }
}

// ---------------------------------------------------------------------------
// tf32 dense GCN propagation — A tiles loaded as uint8, expanded to tf32 one-bits
// ---------------------------------------------------------------------------
template <bool RELU>
__global__ __launch_bounds__(256) void k_prop_tf32(
        const unsigned char* __restrict__ Adj8, const float* __restrict__ XW,
        const float* __restrict__ dis, const float* __restrict__ bias,
        float* __restrict__ out, int F, int outStride, int outOffset) {
    __shared__ uint32_t As[2][16][136];
    __shared__ uint32_t Bs[2][16][136];
    int b = blockIdx.z;
    const unsigned char* Ab = Adj8 + (long)b * kN * kN;
    const float* Xb = XW + (long)b * kN * F;
    const float* db = dis + b * kN;
    float* Ob = out + (long)b * kN * outStride + outOffset;
    int i0 = blockIdx.y * 128, f0 = blockIdx.x * 128;
    int t = threadIdx.x;
    int wid = t >> 5, lane = t & 31;
    int mw = (wid >> 1) * 32, nw = (wid & 1) * 64;
    int g = lane >> 2, tg = lane & 3;
    int jj = t >> 4;
    int ii = (t & 15) << 3;

    float acc[2][8][4];
#pragma unroll
    for (int i = 0; i < 2; i++)
#pragma unroll
        for (int j = 0; j < 8; j++)
#pragma unroll
            for (int c = 0; c < 4; c++) acc[i][j][c] = 0.f;

    constexpr uint32_t ONE = 0x3F800000u;
    auto stTile = [&](int bufI, uint2 rawA, float4 x0, float4 x1, float dj) {
        uint4 ua0, ua1, ux0, ux1;
        ua0.x = (rawA.x & 0xffu)         ? ONE : 0u;
        ua0.y = ((rawA.x >> 8) & 0xffu)  ? ONE : 0u;
        ua0.z = ((rawA.x >> 16) & 0xffu) ? ONE : 0u;
        ua0.w = ((rawA.x >> 24) & 0xffu) ? ONE : 0u;
        ua1.x = (rawA.y & 0xffu)         ? ONE : 0u;
        ua1.y = ((rawA.y >> 8) & 0xffu)  ? ONE : 0u;
        ua1.z = ((rawA.y >> 16) & 0xffu) ? ONE : 0u;
        ua1.w = ((rawA.y >> 24) & 0xffu) ? ONE : 0u;
        ux0.x = f2tf(x0.x * dj); ux0.y = f2tf(x0.y * dj);
        ux0.z = f2tf(x0.z * dj); ux0.w = f2tf(x0.w * dj);
        ux1.x = f2tf(x1.x * dj); ux1.y = f2tf(x1.y * dj);
        ux1.z = f2tf(x1.z * dj); ux1.w = f2tf(x1.w * dj);
        *reinterpret_cast<uint4*>(&As[bufI][jj][ii]) = ua0;
        *reinterpret_cast<uint4*>(&As[bufI][jj][ii + 4]) = ua1;
        *reinterpret_cast<uint4*>(&Bs[bufI][jj][ii]) = ux0;
        *reinterpret_cast<uint4*>(&Bs[bufI][jj][ii + 4]) = ux1;
    };

    {
        uint2 rawA = *reinterpret_cast<const uint2*>(Ab + (long)jj * kN + i0 + ii);
        const float* xp = Xb + (long)jj * F + f0 + ii;
        stTile(0, rawA,
               *reinterpret_cast<const float4*>(xp),
               *reinterpret_cast<const float4*>(xp + 4),
               db[jj]);
    }
    __syncthreads();

    int buf = 0;
    for (int j0 = 0; j0 < kN; j0 += 16) {
        bool more = (j0 + 16) < kN;
        uint2 nraw;
        float4 nx0, nx1;
        float djn = 0.f;
        if (more) {
            nraw = *reinterpret_cast<const uint2*>(
                Ab + (long)(j0 + 16 + jj) * kN + i0 + ii);
            const float* xp = Xb + (long)(j0 + 16 + jj) * F + f0 + ii;
            nx0 = *reinterpret_cast<const float4*>(xp);
            nx1 = *reinterpret_cast<const float4*>(xp + 4);
            djn = db[j0 + 16 + jj];
        }
#pragma unroll
        for (int s = 0; s < 2; s++) {
            int kk = s * 8 + tg;
            uint32_t af[2][4];
#pragma unroll
            for (int mt = 0; mt < 2; mt++) {
                int m = mw + mt * 16 + g;
                af[mt][0] = As[buf][kk][m];
                af[mt][1] = As[buf][kk][m + 8];
                af[mt][2] = As[buf][kk + 4][m];
                af[mt][3] = As[buf][kk + 4][m + 8];
            }
#pragma unroll
            for (int j = 0; j < 8; j++) {
                int n = nw + j * 8 + g;
                uint32_t b0 = Bs[buf][kk][n];
                uint32_t b1 = Bs[buf][kk + 4][n];
                mma_tf32(acc[0][j], af[0], b0, b1);
                mma_tf32(acc[1][j], af[1], b0, b1);
            }
        }
        if (more) {
            int nb = buf ^ 1;
            stTile(nb, nraw, nx0, nx1, djn);
            __syncthreads();
            buf = nb;
        }
    }

#pragma unroll
    for (int mt = 0; mt < 2; mt++) {
        int rowA = i0 + mw + mt * 16 + g;
        float diA = db[rowA], diB = db[rowA + 8];
#pragma unroll
        for (int j = 0; j < 8; j++) {
            int col = f0 + nw + j * 8 + 2 * tg;
            float2 bb = *reinterpret_cast<const float2*>(bias + col);
            float2 xA = *reinterpret_cast<const float2*>(Xb + (long)rowA * F + col);
            float2 xB = *reinterpret_cast<const float2*>(Xb + (long)(rowA + 8) * F + col);
            float v0 = diA * (acc[mt][j][0] + diA * xA.x) + bb.x;
            float v1 = diA * (acc[mt][j][1] + diA * xA.y) + bb.y;
            float v2 = diB * (acc[mt][j][2] + diB * xB.x) + bb.x;
            float v3 = diB * (acc[mt][j][3] + diB * xB.y) + bb.y;
            if (RELU) {
                v0 = fmaxf(v0, 0.f); v1 = fmaxf(v1, 0.f);
                v2 = fmaxf(v2, 0.f); v3 = fmaxf(v3, 0.f);
            }
            *reinterpret_cast<float2*>(Ob + (long)rowA * outStride + col) =
                make_float2(v0, v1);
            *reinterpret_cast<float2*>(Ob + (long)(rowA + 8) * outStride + col) =
                make_float2(v2, v3);
        }
    }
}

// ---------------------------------------------------------------------------
// fcn1 split-K + head
// ---------------------------------------------------------------------------
__global__ void k_fcn1(const float* __restrict__ emb, const float* __restrict__ W,
                       float* __restrict__ h1) {
    constexpr int KC = kKTOT / 128;
    __shared__ float As[16][32];
    __shared__ float Bs[16][64];
    int n0 = blockIdx.x * 64;
    int kbase = blockIdx.y * KC;
    int t = threadIdx.x;
    int m = t & 31;
    int nb = (t >> 5) << 3;
    float acc[8];
#pragma unroll
    for (int j = 0; j < 8; j++) acc[j] = 0.f;

    for (int k0 = kbase; k0 < kbase + KC; k0 += 16) {
        if (t < 128) {
            int row = t >> 2, c4 = (t & 3) << 2;
            float4 a = *reinterpret_cast<const float4*>(emb + (long)row * kKTOT + k0 + c4);
            As[c4 + 0][row] = a.x; As[c4 + 1][row] = a.y;
            As[c4 + 2][row] = a.z; As[c4 + 3][row] = a.w;
        }
        {
            int row = t >> 2, c4 = (t & 3) << 2;
            float4 b = *reinterpret_cast<const float4*>(W + (long)(n0 + row) * kKTOT + k0 + c4);
            Bs[c4 + 0][row] = b.x; Bs[c4 + 1][row] = b.y;
            Bs[c4 + 2][row] = b.z; Bs[c4 + 3][row] = b.w;
        }
        __syncthreads();
#pragma unroll
        for (int k = 0; k < 16; k++) {
            float a = As[k][m];
#pragma unroll
            for (int j = 0; j < 8; j++) acc[j] += a * Bs[k][nb + j];
        }
        __syncthreads();
    }
#pragma unroll
    for (int j = 0; j < 8; j++)
        atomicAdd(&h1[m * 256 + n0 + nb + j], acc[j]);
}

__global__ void k_fcn23(const float* __restrict__ h1g,
                        const float* __restrict__ b1, const float* __restrict__ w2,
                        const float* __restrict__ b2, const float* __restrict__ w3,
                        const float* __restrict__ b3, float* __restrict__ out) {
    __shared__ float h1s[32][256];
    __shared__ float h2s[32][32];
    int t = threadIdx.x;
    for (int idx = t; idx < 32 * 256; idx += 1024) {
        float v = h1g[idx] + b1[idx & 255];
        h1s[idx >> 8][idx & 255] = (v >= 0.f) ? v : 0.2f * v;
    }
    __syncthreads();
    {
        int b = t >> 5, o = t & 31;
        float s = 0.f;
#pragma unroll 8
        for (int k = 0; k < 256; k++) s += h1s[b][k] * w2[o * 256 + k];
        s += b2[o];
        h2s[b][o] = (s >= 0.f) ? s : 0.2f * s;
    }
    __syncthreads();
    if (t < 64) {
        int b = t >> 1, o = t & 1;
        float s = 0.f;
#pragma unroll
        for (int k = 0; k < 32; k++) s += h2s[b][k] * w3[o * 32 + k];
        out[b * 2 + o] = s + b3[o];
    }
}

// ---------------------------------------------------------------------------
// Launch
// ---------------------------------------------------------------------------
extern "C" void kernel_launch(void* const* d_in, const int* in_sizes, int n_in,
                              void* d_out, int out_size) {
    const float* x    = (const float*)d_in[0];
    const float* t    = (const float*)d_in[1];
    const float* gu   = (const float*)d_in[2];
    const int*   ei   = (const int*)d_in[3];
    const float* w1   = (const float*)d_in[4];
    const float* b1   = (const float*)d_in[5];
    const float* w2   = (const float*)d_in[6];
    const float* b2   = (const float*)d_in[7];
    const float* fcw  = (const float*)d_in[8];
    const float* fcb  = (const float*)d_in[9];
    const float* f1w  = (const float*)d_in[10];
    const float* f1b  = (const float*)d_in[11];
    const float* f2w  = (const float*)d_in[12];
    const float* f2b  = (const float*)d_in[13];
    const float* f3w  = (const float*)d_in[14];
    const float* f3b  = (const float*)d_in[15];
    float* out = (float*)d_out;

    const int* rowp = ei;
    const int* colp = ei + kE;

    float* base = nullptr;
    cudaGetSymbolAddress((void**)&base, g_scratch);
    float* p_E    = base + OFF_EG;
    float* p_F    = base + OFF_FG;
    unsigned char* p_A8 = (unsigned char*)(base + OFF_A8);
    float* p_disD = base + OFF_DISD;
    float* p_xw1  = base + OFF_XW1;     // shared by dense prop1 AND sparse gather1
    float* p_h    = base + OFF_H;
    float* p_xw2  = base + OFF_XW2;
    float* p_emb  = base + OFF_EMB;
    float* p_disS = base + OFF_DISS;
    int*   p_degS = (int*)(base + OFF_DEGS);
    float* p_sc1  = base + OFF_SC1;
    float* p_xws2 = base + OFF_XWS2;
    float* p_h1   = base + OFF_H1;
    float* p_degD = base + OFF_DEGD;
    int*   p_ns   = (int*)(base + OFF_NS);
    int*   p_cur  = (int*)(base + OFF_CUR);
    int*   p_esrc = (int*)(base + OFF_ESRC);

    // 0-2: adjacency prep
    k_zero<<<64, 256>>>(p_degS, p_h1, p_degD);
    k_lslr<<<kNTOT / 8, 256>>>(t, fcw, fcb, p_E, p_F);
    k_buildA<<<kBZ * kN * kN / 1024, 256>>>(gu, p_E, p_F, p_A8);

    // 3: shared layer-1 feature GEMM (dense AND sparse), flat M=16384
    //    (placed here so the profiler's captured launch is this GEMM)
    k_gemm_tf32<false><<<dim3(kF1 / 128, kNTOT / 128, 1), 256>>>(
        x, 0, w1, p_xw1, 0, kF1, kN);

    // 4-8: degrees + CSR
    k_colsum_part<<<dim3(kBZ, 8), kN>>>(p_A8, p_degD);
    k_degS<<<kE / 256, 256>>>(colp, p_degS);
    k_dis<<<kNTOT / 256, 256>>>(p_degD, p_degS, p_disD, p_disS);
    k_scan<<<1, 1024>>>(p_degS, p_ns, p_cur);
    k_fill<<<kE / 256, 256>>>(rowp, colp, p_cur, p_esrc);

    // dense GCN
    k_prop_tf32<true><<<dim3(kF1 / 128, kN / 128, kBZ), 256>>>(
        p_A8, p_xw1, p_disD, b1, p_h, kF1, kF1, 0);
    k_gemm_tf32<false><<<dim3(kF2 / 128, kN / 128, kBZ), 256>>>(
        p_h, (long)kN * kF1, w2, p_xw2, (long)kN * kF2, kF2, kF1);
    k_prop_tf32<false><<<dim3(kF2 / 128, kN / 128, kBZ), 256>>>(
        p_A8, p_xw2, p_disD, b2, p_emb, kF2, 256, 0);

    // sparse GCN (gather uses the shared p_xw1)
    k_gather<2><<<kNTOT * 2 / 8, 256>>>(p_ns, p_esrc, p_xw1, p_disS, b1,
                                        p_sc1, kF1, 0);
    k_gemm_tf32<true><<<dim3(kF2 / 128, kNTOT / 128, 1), 256>>>(
        p_sc1, 0, w2, p_xws2, 0, kF2, kF1);
    k_gather<1><<<kNTOT / 8, 256>>>(p_ns, p_esrc, p_xws2, p_disS, b2,
                                    p_emb, 256, 128);

    // MLP head
    k_fcn1<<<dim3(256 / 64, 128), 256>>>(p_emb, f1w, p_h1);
    k_fcn23<<<1, 1024>>>(p_h1, f1b, f2w, f2b, f3w, f3b, out);
}